// round 2
// baseline (speedup 1.0000x reference)
#include <cuda_runtime.h>

#define C 64
#define KSZ 27
#define TM 64
#define NMAX 100000
#define EPSV 1e-5f

// Scratch + stats (device globals: no allocation allowed)
__device__ float g_y1[NMAX * C];
__device__ float g_sum1[C], g_sq1[C], g_sum2[C], g_sq2[C];
__device__ float g_scale1[C], g_shift1[C], g_scale2[C], g_shift2[C];

__global__ void zero_stats_kernel() {
    int t = threadIdx.x;
    if (t < C) { g_sum1[t] = 0.f; g_sq1[t] = 0.f; g_sum2[t] = 0.f; g_sq2[t] = 0.f; }
}

// One sparse-conv pass: out[n,d] = sum_k sum_c in[nbr[n,k],c] * W[k,c,d] + b[d]
// PASS==1 additionally applies BN1+ReLU to the gathered input on the fly.
// Also accumulates per-channel sum / sumsq of the (biased) output for BN stats.
template<int PASS>
__global__ __launch_bounds__(256) void conv_kernel(
    const float* __restrict__ feats, const int* __restrict__ nbr,
    const float* __restrict__ W, const float* __restrict__ bias,
    float* __restrict__ dout, int n)
{
    __shared__ float As[TM][C];      // gathered input tile [64 rows][64 ch]
    __shared__ float Ws[C][C];       // W[k] tile
    __shared__ int   rows[TM];
    __shared__ float s_sum[C], s_sq[C];
    __shared__ float s_scale[C], s_shift[C];

    const float* src  = (PASS == 0) ? feats  : g_y1;
    float*       yout = (PASS == 0) ? g_y1   : dout;
    float*       gsum = (PASS == 0) ? g_sum1 : g_sum2;
    float*       gsq  = (PASS == 0) ? g_sq1  : g_sq2;

    const int tid = threadIdx.x;
    const int tx = tid & 15, ty = tid >> 4;
    const int c0 = tx * 4, r0 = ty * 4;
    const long row_base = (long)blockIdx.x * TM;

    if (tid < C) {
        s_sum[tid] = 0.f; s_sq[tid] = 0.f;
        if (PASS == 1) { s_scale[tid] = g_scale1[tid]; s_shift[tid] = g_shift1[tid]; }
    }

    float acc[4][4];
    #pragma unroll
    for (int i = 0; i < 4; ++i)
        #pragma unroll
        for (int j = 0; j < 4; ++j) acc[i][j] = 0.f;

    for (int k = 0; k < KSZ; ++k) {
        __syncthreads();   // previous-iteration compute done (also covers s_* init on k=0)

        if (tid < TM) {
            long r = row_base + tid;
            rows[tid] = (r < (long)n) ? nbr[r * KSZ + k] : -1;
        }
        {   // stage W[k]: 4096 floats, coalesced float4
            const float4* Wg = (const float4*)(W + (long)k * C * C);
            float4* Ws4 = (float4*)Ws;
            #pragma unroll
            for (int i = 0; i < 4; ++i) Ws4[tid + i * 256] = Wg[tid + i * 256];
        }
        __syncthreads();   // rows[] visible

        // gather A tile: 64 rows x 16 float4, random rows but L2-resident
        #pragma unroll
        for (int i = 0; i < 4; ++i) {
            int idx = tid + i * 256;       // 0..1023
            int r = idx >> 4, seg = idx & 15;
            int sr = rows[r];
            float4 v = make_float4(0.f, 0.f, 0.f, 0.f);
            if (sr >= 0) {
                v = ((const float4*)(src + (long)sr * C))[seg];
                if (PASS == 1) {
                    int c = seg * 4;
                    v.x = fmaxf(fmaf(v.x, s_scale[c + 0], s_shift[c + 0]), 0.f);
                    v.y = fmaxf(fmaf(v.y, s_scale[c + 1], s_shift[c + 1]), 0.f);
                    v.z = fmaxf(fmaf(v.z, s_scale[c + 2], s_shift[c + 2]), 0.f);
                    v.w = fmaxf(fmaf(v.w, s_scale[c + 3], s_shift[c + 3]), 0.f);
                }
            }
            *((float4*)&As[r][seg * 4]) = v;
        }
        __syncthreads();   // As + Ws visible

        // 64x64x64 fragment: 4x4 register micro-tile per thread
        #pragma unroll 16
        for (int cc = 0; cc < C; ++cc) {
            float a0 = As[r0 + 0][cc];
            float a1 = As[r0 + 1][cc];
            float a2 = As[r0 + 2][cc];
            float a3 = As[r0 + 3][cc];
            float4 b = *((const float4*)&Ws[cc][c0]);
            acc[0][0] = fmaf(a0, b.x, acc[0][0]); acc[0][1] = fmaf(a0, b.y, acc[0][1]);
            acc[0][2] = fmaf(a0, b.z, acc[0][2]); acc[0][3] = fmaf(a0, b.w, acc[0][3]);
            acc[1][0] = fmaf(a1, b.x, acc[1][0]); acc[1][1] = fmaf(a1, b.y, acc[1][1]);
            acc[1][2] = fmaf(a1, b.z, acc[1][2]); acc[1][3] = fmaf(a1, b.w, acc[1][3]);
            acc[2][0] = fmaf(a2, b.x, acc[2][0]); acc[2][1] = fmaf(a2, b.y, acc[2][1]);
            acc[2][2] = fmaf(a2, b.z, acc[2][2]); acc[2][3] = fmaf(a2, b.w, acc[2][3]);
            acc[3][0] = fmaf(a3, b.x, acc[3][0]); acc[3][1] = fmaf(a3, b.y, acc[3][1]);
            acc[3][2] = fmaf(a3, b.z, acc[3][2]); acc[3][3] = fmaf(a3, b.w, acc[3][3]);
        }
    }

    // epilogue: bias, store, BN partial stats
    float b0 = bias[c0 + 0], b1 = bias[c0 + 1], b2 = bias[c0 + 2], b3 = bias[c0 + 3];
    float csum[4] = {0.f, 0.f, 0.f, 0.f};
    float csq[4]  = {0.f, 0.f, 0.f, 0.f};
    #pragma unroll
    for (int i = 0; i < 4; ++i) {
        long r = row_base + r0 + i;
        if (r < (long)n) {
            float4 o;
            o.x = acc[i][0] + b0; o.y = acc[i][1] + b1;
            o.z = acc[i][2] + b2; o.w = acc[i][3] + b3;
            ((float4*)(yout + r * C))[tx] = o;
            csum[0] += o.x; csq[0] += o.x * o.x;
            csum[1] += o.y; csq[1] += o.y * o.y;
            csum[2] += o.z; csq[2] += o.z * o.z;
            csum[3] += o.w; csq[3] += o.w * o.w;
        }
    }
    #pragma unroll
    for (int j = 0; j < 4; ++j) {
        atomicAdd(&s_sum[c0 + j], csum[j]);
        atomicAdd(&s_sq[c0 + j],  csq[j]);
    }
    __syncthreads();
    if (tid < C) {
        atomicAdd(&gsum[tid], s_sum[tid]);
        atomicAdd(&gsq[tid],  s_sq[tid]);
    }
}

template<int PASS>
__global__ void stats_kernel(const float* __restrict__ gamma,
                             const float* __restrict__ beta, int n) {
    int d = threadIdx.x;
    if (d >= C) return;
    float sum = (PASS == 0) ? g_sum1[d] : g_sum2[d];
    float sq  = (PASS == 0) ? g_sq1[d]  : g_sq2[d];
    float inv_n = 1.0f / (float)n;
    float mean = sum * inv_n;
    float var = fmaxf(sq * inv_n - mean * mean, 0.f);
    float sc = gamma[d] * rsqrtf(var + EPSV);
    float sh = beta[d] - mean * sc;
    if (PASS == 0) { g_scale1[d] = sc; g_shift1[d] = sh; }
    else           { g_scale2[d] = sc; g_shift2[d] = sh; }
}

// out = relu(bn2(y2) + feats), in place on d_out (which holds y2)
__global__ void final_kernel(const float* __restrict__ feats,
                             float* __restrict__ out, int n) {
    int i = blockIdx.x * blockDim.x + threadIdx.x;   // float4 index
    int total = n * (C / 4);
    if (i >= total) return;
    int c = (i & 15) * 4;
    float4 y = ((const float4*)out)[i];
    float4 f = ((const float4*)feats)[i];
    float4 r;
    r.x = fmaxf(fmaf(y.x, g_scale2[c + 0], g_shift2[c + 0]) + f.x, 0.f);
    r.y = fmaxf(fmaf(y.y, g_scale2[c + 1], g_shift2[c + 1]) + f.y, 0.f);
    r.z = fmaxf(fmaf(y.z, g_scale2[c + 2], g_shift2[c + 2]) + f.z, 0.f);
    r.w = fmaxf(fmaf(y.w, g_scale2[c + 3], g_shift2[c + 3]) + f.w, 0.f);
    ((float4*)out)[i] = r;
}

extern "C" void kernel_launch(void* const* d_in, const int* in_sizes, int n_in,
                              void* d_out, int out_size) {
    const float* feats = (const float*)d_in[0];
    const int*   nbr   = (const int*)d_in[1];
    const float* W1    = (const float*)d_in[2];
    const float* b1    = (const float*)d_in[3];
    const float* g1    = (const float*)d_in[4];
    const float* be1   = (const float*)d_in[5];
    const float* W2    = (const float*)d_in[6];
    const float* b2    = (const float*)d_in[7];
    const float* g2    = (const float*)d_in[8];
    const float* be2   = (const float*)d_in[9];
    float* out = (float*)d_out;

    int n = in_sizes[0] / C;
    int conv_blocks = (n + TM - 1) / TM;
    int ew_blocks = (n * (C / 4) + 255) / 256;

    zero_stats_kernel<<<1, 64>>>();
    conv_kernel<0><<<conv_blocks, 256>>>(feats, nbr, W1, b1, nullptr, n);
    stats_kernel<0><<<1, 64>>>(g1, be1, n);
    conv_kernel<1><<<conv_blocks, 256>>>(feats, nbr, W2, b2, out, n);
    stats_kernel<1><<<1, 64>>>(g2, be2, n);
    final_kernel<<<ew_blocks, 256>>>(feats, out, n);
}

// round 4
// speedup vs baseline: 1.5045x; 1.5045x over previous
#include <cuda_runtime.h>
#include <cstdint>

#define C 64
#define KSZ 27
#define TM 128
#define NMAX 100000
#define EPSV 1e-5f

// SMEM layout (bytes, within dynamic smem after 1KB alignment)
#define A_STRIDE 144              // 64 bf16 (128B) + 16B pad -> conflict-free ldmatrix
#define SM_AH 0
#define SM_AL (128 * 144)         // 18432
#define SM_WH (2 * 128 * 144)     // 36864
#define SM_WL (2 * 128 * 144 + 64 * 144)
#define SMEM_DYN (2 * 128 * 144 + 2 * 64 * 144 + 1024)   // 56320 incl. align pad

// Device scratch (no allocation allowed)
__device__ float g_y1[NMAX * C];
__device__ float g_sum1[C], g_sq1[C], g_sum2[C], g_sq2[C];
__device__ float g_scale1[C], g_shift1[C], g_scale2[C], g_shift2[C];
// weights transposed to [conv][k][d][c], bf16 hi/lo
__device__ __align__(16) unsigned short g_wt_hi[2 * KSZ * C * C];
__device__ __align__(16) unsigned short g_wt_lo[2 * KSZ * C * C];

// ---------------- helpers ----------------
static __device__ __forceinline__ uint32_t smem_u32(const void* p) {
    uint32_t a;
    asm("{ .reg .u64 t; cvta.to.shared.u64 t, %1; cvt.u32.u64 %0, t; }" : "=r"(a) : "l"(p));
    return a;
}
// pack two fp32 -> bf16x2 {upper=hi_arg, lower=lo_arg}
static __device__ __forceinline__ uint32_t pack_bf16(float up, float lo) {
    uint32_t r;
    asm("cvt.rn.bf16x2.f32 %0, %1, %2;" : "=r"(r) : "f"(up), "f"(lo));
    return r;
}
static __device__ __forceinline__ void sts128(uint32_t a, uint4 v) {
    asm volatile("st.shared.v4.b32 [%0], {%1,%2,%3,%4};"
                 :: "r"(a), "r"(v.x), "r"(v.y), "r"(v.z), "r"(v.w) : "memory");
}
static __device__ __forceinline__ void ldm4(uint32_t* r, uint32_t addr) {
    asm volatile("ldmatrix.sync.aligned.m8n8.x4.shared.b16 {%0,%1,%2,%3}, [%4];"
                 : "=r"(r[0]), "=r"(r[1]), "=r"(r[2]), "=r"(r[3]) : "r"(addr));
}
static __device__ __forceinline__ void ldm2(uint32_t* r, uint32_t addr) {
    asm volatile("ldmatrix.sync.aligned.m8n8.x2.shared.b16 {%0,%1}, [%2];"
                 : "=r"(r[0]), "=r"(r[1]) : "r"(addr));
}
static __device__ __forceinline__ void mma_bf16(float* c, const uint32_t* a, const uint32_t* b) {
    asm volatile(
        "mma.sync.aligned.m16n8k16.row.col.f32.bf16.bf16.f32 "
        "{%0,%1,%2,%3}, {%4,%5,%6,%7}, {%8,%9}, {%0,%1,%2,%3};"
        : "+f"(c[0]), "+f"(c[1]), "+f"(c[2]), "+f"(c[3])
        : "r"(a[0]), "r"(a[1]), "r"(a[2]), "r"(a[3]), "r"(b[0]), "r"(b[1]));
}

// ---------------- kernels ----------------
__global__ void zero_stats_kernel() {
    int t = threadIdx.x;
    if (t < C) { g_sum1[t] = 0.f; g_sq1[t] = 0.f; g_sum2[t] = 0.f; g_sq2[t] = 0.f; }
}

// Split + transpose weights: g_wt[conv][k][d][c] (bf16 hi/lo), rows of 64 bf16.
__global__ void prep_w_kernel(const float* __restrict__ W1, const float* __restrict__ W2) {
    int b = blockIdx.x;             // 0..2*KSZ-1
    int conv = b / KSZ, k = b % KSZ;
    const float* W = (conv == 0) ? W1 : W2;
    for (int i = threadIdx.x; i < C * C; i += blockDim.x) {
        int c = i >> 6, d = i & 63;
        float v = W[k * C * C + c * C + d];
        uint32_t hb = pack_bf16(0.f, v) & 0xffffu;
        float hf = __uint_as_float(hb << 16);
        uint32_t lb = pack_bf16(0.f, v - hf) & 0xffffu;
        uint32_t idx = (uint32_t)(conv * KSZ + k) * 4096u + (uint32_t)d * 64u + (uint32_t)c;
        g_wt_hi[idx] = (unsigned short)hb;
        g_wt_lo[idx] = (unsigned short)lb;
    }
}

template<int PASS>
__global__ __launch_bounds__(256) void conv_mma_kernel(
    const float* __restrict__ feats, const int* __restrict__ nbr,
    const float* __restrict__ bias, float* __restrict__ dout, int n)
{
    extern __shared__ char dsm[];
    __shared__ float s_scale[C], s_shift[C], s_sum[C], s_sq[C], s_bias[C];

    const float* src  = (PASS == 0) ? feats  : g_y1;
    float*       yout = (PASS == 0) ? g_y1   : dout;
    float*       gsum = (PASS == 0) ? g_sum1 : g_sum2;
    float*       gsq  = (PASS == 0) ? g_sq1  : g_sq2;

    const int tid = threadIdx.x, lane = tid & 31, w = tid >> 5;
    const uint32_t base = (smem_u32(dsm) + 1023u) & ~1023u;

    if (tid < C) {
        s_sum[tid] = 0.f; s_sq[tid] = 0.f; s_bias[tid] = bias[tid];
        if (PASS == 1) { s_scale[tid] = g_scale1[tid]; s_shift[tid] = g_shift1[tid]; }
    }

    // gather role: each thread owns half a row (32 channels)
    const int grow = tid >> 1;               // 0..127
    const int ghalf = tid & 1;               // channel half
    const long rowg = (long)blockIdx.x * TM + grow;
    const bool gvalid = rowg < (long)n;
    const uint32_t a_st_h = base + SM_AH + (uint32_t)grow * A_STRIDE + (uint32_t)ghalf * 64u;
    const uint32_t a_st_l = base + SM_AL + (uint32_t)grow * A_STRIDE + (uint32_t)ghalf * 64u;

    // mma role: warp w owns rows w*16..w*16+15
    const uint32_t a_ld_h = base + SM_AH + (uint32_t)(w * 16 + (lane & 15)) * A_STRIDE
                            + (uint32_t)((lane >> 4) << 4);
    const uint32_t a_ld_l = a_ld_h + (SM_AL - SM_AH);
    const int brow = lane & 7, bhalf = (lane >> 3) & 1;

    float acc[8][4];
    #pragma unroll
    for (int nt = 0; nt < 8; ++nt)
        #pragma unroll
        for (int j = 0; j < 4; ++j) acc[nt][j] = 0.f;

    for (int k = 0; k < KSZ; ++k) {
        __syncthreads();   // smem free (also covers s_* init at k=0)

        // stage W[k] hi/lo into padded smem (8 uint4 per 64-bf16 row)
        {
            const uint4* gh = (const uint4*)g_wt_hi + (size_t)(PASS * KSZ + k) * 512;
            const uint4* gl = (const uint4*)g_wt_lo + (size_t)(PASS * KSZ + k) * 512;
            #pragma unroll
            for (int i = 0; i < 2; ++i) {
                int j = tid + i * 256;                 // 0..511
                uint32_t dst = (uint32_t)(j >> 3) * A_STRIDE + (uint32_t)(j & 7) * 16u;
                sts128(base + SM_WH + dst, gh[j]);
                sts128(base + SM_WL + dst, gl[j]);
            }
        }
        // gather 32 fp32 channels, optional BN1+ReLU, split to bf16 hi/lo
        {
            int sr = gvalid ? nbr[rowg * KSZ + k] : -1;
            float f[32];
            if (sr >= 0) {
                const float4* p4 = (const float4*)(src + (size_t)sr * C + ghalf * 32);
                #pragma unroll
                for (int q = 0; q < 8; ++q) {
                    float4 u = p4[q];
                    f[4 * q + 0] = u.x; f[4 * q + 1] = u.y;
                    f[4 * q + 2] = u.z; f[4 * q + 3] = u.w;
                }
                if (PASS == 1) {
                    #pragma unroll
                    for (int j = 0; j < 32; ++j) {
                        int ch = ghalf * 32 + j;
                        f[j] = fmaxf(fmaf(f[j], s_scale[ch], s_shift[ch]), 0.f);
                    }
                }
            } else {
                #pragma unroll
                for (int j = 0; j < 32; ++j) f[j] = 0.f;
            }
            #pragma unroll
            for (int s = 0; s < 4; ++s) {
                uint32_t h[4], l[4];
                #pragma unroll
                for (int j = 0; j < 4; ++j) {
                    float x0 = f[s * 8 + 2 * j], x1 = f[s * 8 + 2 * j + 1];
                    h[j] = pack_bf16(x1, x0);
                    float h0 = __uint_as_float(h[j] << 16);
                    float h1 = __uint_as_float(h[j] & 0xffff0000u);
                    l[j] = pack_bf16(x1 - h1, x0 - h0);
                }
                sts128(a_st_h + s * 16u, make_uint4(h[0], h[1], h[2], h[3]));
                sts128(a_st_l + s * 16u, make_uint4(l[0], l[1], l[2], l[3]));
            }
        }
        __syncthreads();

        // 128x64x64 via m16n8k16, 3-term bf16 split
        #pragma unroll
        for (int kk = 0; kk < 4; ++kk) {
            uint32_t ah[4], al[4];
            ldm4(ah, a_ld_h + kk * 32u);
            ldm4(al, a_ld_l + kk * 32u);
            #pragma unroll
            for (int nt = 0; nt < 8; ++nt) {
                uint32_t bh[2], bl[2];
                uint32_t boff = (uint32_t)(nt * 8 + brow) * A_STRIDE
                                + (uint32_t)bhalf * 16u + (uint32_t)kk * 32u;
                ldm2(bh, base + SM_WH + boff);
                ldm2(bl, base + SM_WL + boff);
                mma_bf16(acc[nt], ah, bh);
                mma_bf16(acc[nt], ah, bl);
                mma_bf16(acc[nt], al, bh);
            }
        }
    }

    // ---------------- epilogue ----------------
    const int g = lane >> 2, tig = lane & 3;
    const long row0 = (long)blockIdx.x * TM + w * 16 + g;
    const long row1 = row0 + 8;
    const bool v0 = row0 < (long)n, v1 = row1 < (long)n;

    #pragma unroll
    for (int nt = 0; nt < 8; ++nt) {
        int col = nt * 8 + tig * 2;
        float b0 = s_bias[col], b1 = s_bias[col + 1];
        float y00 = v0 ? acc[nt][0] + b0 : 0.f;
        float y01 = v0 ? acc[nt][1] + b1 : 0.f;
        float y10 = v1 ? acc[nt][2] + b0 : 0.f;
        float y11 = v1 ? acc[nt][3] + b1 : 0.f;
        if (v0) *(float2*)(yout + (size_t)row0 * C + col) = make_float2(y00, y01);
        if (v1) *(float2*)(yout + (size_t)row1 * C + col) = make_float2(y10, y11);
        // BN partials: reduce over the 16 rows of this warp (lanes with same tig)
        float sv0 = y00 + y10, sv1 = y01 + y11;
        float sq0 = y00 * y00 + y10 * y10, sq1 = y01 * y01 + y11 * y11;
        #pragma unroll
        for (int o = 16; o >= 4; o >>= 1) {
            sv0 += __shfl_xor_sync(0xffffffffu, sv0, o);
            sv1 += __shfl_xor_sync(0xffffffffu, sv1, o);
            sq0 += __shfl_xor_sync(0xffffffffu, sq0, o);
            sq1 += __shfl_xor_sync(0xffffffffu, sq1, o);
        }
        if (lane < 4) {
            atomicAdd(&s_sum[col], sv0); atomicAdd(&s_sum[col + 1], sv1);
            atomicAdd(&s_sq[col],  sq0); atomicAdd(&s_sq[col + 1],  sq1);
        }
    }
    __syncthreads();
    if (tid < C) { atomicAdd(&gsum[tid], s_sum[tid]); atomicAdd(&gsq[tid], s_sq[tid]); }
}

template<int PASS>
__global__ void stats_kernel(const float* __restrict__ gamma,
                             const float* __restrict__ beta, int n) {
    int d = threadIdx.x;
    if (d >= C) return;
    float sum = (PASS == 0) ? g_sum1[d] : g_sum2[d];
    float sq  = (PASS == 0) ? g_sq1[d]  : g_sq2[d];
    float inv_n = 1.0f / (float)n;
    float mean = sum * inv_n;
    float var = fmaxf(sq * inv_n - mean * mean, 0.f);
    float sc = gamma[d] * rsqrtf(var + EPSV);
    float sh = beta[d] - mean * sc;
    if (PASS == 0) { g_scale1[d] = sc; g_shift1[d] = sh; }
    else           { g_scale2[d] = sc; g_shift2[d] = sh; }
}

__global__ void final_kernel(const float* __restrict__ feats,
                             float* __restrict__ out, int n) {
    int i = blockIdx.x * blockDim.x + threadIdx.x;
    int total = n * (C / 4);
    if (i >= total) return;
    int c = (i & 15) * 4;
    float4 y = ((const float4*)out)[i];
    float4 f = ((const float4*)feats)[i];
    float4 r;
    r.x = fmaxf(fmaf(y.x, g_scale2[c + 0], g_shift2[c + 0]) + f.x, 0.f);
    r.y = fmaxf(fmaf(y.y, g_scale2[c + 1], g_shift2[c + 1]) + f.y, 0.f);
    r.z = fmaxf(fmaf(y.z, g_scale2[c + 2], g_shift2[c + 2]) + f.z, 0.f);
    r.w = fmaxf(fmaf(y.w, g_scale2[c + 3], g_shift2[c + 3]) + f.w, 0.f);
    ((float4*)out)[i] = r;
}

extern "C" void kernel_launch(void* const* d_in, const int* in_sizes, int n_in,
                              void* d_out, int out_size) {
    const float* feats = (const float*)d_in[0];
    const int*   nbr   = (const int*)d_in[1];
    const float* W1    = (const float*)d_in[2];
    const float* b1    = (const float*)d_in[3];
    const float* g1    = (const float*)d_in[4];
    const float* be1   = (const float*)d_in[5];
    const float* W2    = (const float*)d_in[6];
    const float* b2    = (const float*)d_in[7];
    const float* g2    = (const float*)d_in[8];
    const float* be2   = (const float*)d_in[9];
    float* out = (float*)d_out;

    int n = in_sizes[0] / C;
    int conv_blocks = (n + TM - 1) / TM;
    int ew_blocks = (n * (C / 4) + 255) / 256;

    cudaFuncSetAttribute(conv_mma_kernel<0>, cudaFuncAttributeMaxDynamicSharedMemorySize, SMEM_DYN);
    cudaFuncSetAttribute(conv_mma_kernel<1>, cudaFuncAttributeMaxDynamicSharedMemorySize, SMEM_DYN);

    zero_stats_kernel<<<1, 64>>>();
    prep_w_kernel<<<2 * KSZ, 256>>>(W1, W2);
    conv_mma_kernel<0><<<conv_blocks, 256, SMEM_DYN>>>(feats, nbr, b1, nullptr, n);
    stats_kernel<0><<<1, 64>>>(g1, be1, n);
    conv_mma_kernel<1><<<conv_blocks, 256, SMEM_DYN>>>(feats, nbr, b2, out, n);
    stats_kernel<1><<<1, 64>>>(g2, be2, n);
    final_kernel<<<ew_blocks, 256>>>(feats, out, n);
}

// round 5
// speedup vs baseline: 1.6004x; 1.0638x over previous
#include <cuda_runtime.h>
#include <cstdint>

#define C 64
#define KSZ 27
#define TM 128
#define NMAX 100000
#define EPSV 1e-5f

// SMEM layout (bytes, after 1KB alignment)
#define A_STRIDE 144              // 64 bf16 (128B) + 16B pad -> conflict-free ldmatrix
#define SM_AH 0
#define SM_AL (128 * 144)         // 18432
#define SM_W  (2 * 128 * 144)     // 36864: W double buffer, each 18432 (hi 9216 + lo 9216)
#define W_BUF_BYTES (2 * 64 * 144)
#define SMEM_DYN (SM_W + 2 * W_BUF_BYTES + 1024)   // 73728 + pad

// Device scratch (no allocation allowed)
__device__ float g_y1[NMAX * C];
__device__ float g_sum1[C], g_sq1[C], g_sum2[C], g_sq2[C];
__device__ float g_scale1[C], g_shift1[C], g_scale2[C], g_shift2[C];
// weights transposed to [conv][k][d][c], bf16 hi/lo
__device__ __align__(16) unsigned short g_wt_hi[2 * KSZ * C * C];
__device__ __align__(16) unsigned short g_wt_lo[2 * KSZ * C * C];

// ---------------- helpers ----------------
static __device__ __forceinline__ uint32_t smem_u32(const void* p) {
    uint32_t a;
    asm("{ .reg .u64 t; cvta.to.shared.u64 t, %1; cvt.u32.u64 %0, t; }" : "=r"(a) : "l"(p));
    return a;
}
static __device__ __forceinline__ uint32_t pack_bf16(float up, float lo) {
    uint32_t r;
    asm("cvt.rn.bf16x2.f32 %0, %1, %2;" : "=r"(r) : "f"(up), "f"(lo));
    return r;
}
static __device__ __forceinline__ void sts128(uint32_t a, uint4 v) {
    asm volatile("st.shared.v4.b32 [%0], {%1,%2,%3,%4};"
                 :: "r"(a), "r"(v.x), "r"(v.y), "r"(v.z), "r"(v.w) : "memory");
}
static __device__ __forceinline__ void cp_async16(uint32_t dst, const void* src) {
    asm volatile("cp.async.cg.shared.global [%0], [%1], 16;"
                 :: "r"(dst), "l"(__cvta_generic_to_global(src)) : "memory");
}
static __device__ __forceinline__ void cp_commit() {
    asm volatile("cp.async.commit_group;" ::: "memory");
}
static __device__ __forceinline__ void cp_wait0() {
    asm volatile("cp.async.wait_group 0;" ::: "memory");
}
static __device__ __forceinline__ void ldm4(uint32_t* r, uint32_t addr) {
    asm volatile("ldmatrix.sync.aligned.m8n8.x4.shared.b16 {%0,%1,%2,%3}, [%4];"
                 : "=r"(r[0]), "=r"(r[1]), "=r"(r[2]), "=r"(r[3]) : "r"(addr));
}
static __device__ __forceinline__ void mma_bf16(float* c, const uint32_t* a, const uint32_t* b) {
    asm volatile(
        "mma.sync.aligned.m16n8k16.row.col.f32.bf16.bf16.f32 "
        "{%0,%1,%2,%3}, {%4,%5,%6,%7}, {%8,%9}, {%0,%1,%2,%3};"
        : "+f"(c[0]), "+f"(c[1]), "+f"(c[2]), "+f"(c[3])
        : "r"(a[0]), "r"(a[1]), "r"(a[2]), "r"(a[3]), "r"(b[0]), "r"(b[1]));
}

// ---------------- kernels ----------------
__global__ void zero_stats_kernel() {
    int t = threadIdx.x;
    if (t < C) { g_sum1[t] = 0.f; g_sq1[t] = 0.f; g_sum2[t] = 0.f; g_sq2[t] = 0.f; }
}

// Split + transpose weights: g_wt[conv][k][d][c] (bf16 hi/lo), rows of 64 bf16.
__global__ void prep_w_kernel(const float* __restrict__ W1, const float* __restrict__ W2) {
    int b = blockIdx.x;             // 0..2*KSZ-1
    int conv = b / KSZ, k = b % KSZ;
    const float* W = (conv == 0) ? W1 : W2;
    for (int i = threadIdx.x; i < C * C; i += blockDim.x) {
        int c = i >> 6, d = i & 63;
        float v = W[k * C * C + c * C + d];
        uint32_t hb = pack_bf16(0.f, v) & 0xffffu;
        float hf = __uint_as_float(hb << 16);
        uint32_t lb = pack_bf16(0.f, v - hf) & 0xffffu;
        uint32_t idx = (uint32_t)(conv * KSZ + k) * 4096u + (uint32_t)d * 64u + (uint32_t)c;
        g_wt_hi[idx] = (unsigned short)hb;
        g_wt_lo[idx] = (unsigned short)lb;
    }
}

template<int PASS>
__global__ __launch_bounds__(256, 2) void conv_mma_kernel(
    const float* __restrict__ feats, const int* __restrict__ nbr,
    const float* __restrict__ bias, float* __restrict__ dout, int n)
{
    extern __shared__ char dsm[];
    __shared__ float s_scale[C], s_shift[C], s_sum[C], s_sq[C], s_bias[C];

    const float* src  = (PASS == 0) ? feats  : g_y1;
    float*       yout = (PASS == 0) ? g_y1   : dout;
    float*       gsum = (PASS == 0) ? g_sum1 : g_sum2;
    float*       gsq  = (PASS == 0) ? g_sq1  : g_sq2;

    const int tid = threadIdx.x, lane = tid & 31, w = tid >> 5;
    const uint32_t base = (smem_u32(dsm) + 1023u) & ~1023u;

    if (tid < C) {
        s_sum[tid] = 0.f; s_sq[tid] = 0.f; s_bias[tid] = bias[tid];
        if (PASS == 1) { s_scale[tid] = g_scale1[tid]; s_shift[tid] = g_shift1[tid]; }
    }

    // gather role: each thread owns half a row (32 channels)
    const int grow = tid >> 1;
    const int ghalf = tid & 1;
    const long rowg = (long)blockIdx.x * TM + grow;
    const bool gvalid = rowg < (long)n;
    const uint32_t a_st_h = base + SM_AH + (uint32_t)grow * A_STRIDE + (uint32_t)ghalf * 64u;
    const uint32_t a_st_l = base + SM_AL + (uint32_t)grow * A_STRIDE + (uint32_t)ghalf * 64u;

    // mma role: warp w owns rows w*16..w*16+15
    const uint32_t a_ld_h = base + SM_AH + (uint32_t)(w * 16 + (lane & 15)) * A_STRIDE
                            + (uint32_t)((lane >> 4) << 4);
    const uint32_t a_ld_l = a_ld_h + (SM_AL - SM_AH);
    // B ldmatrix.x4: m0/m1 = n-subtile 0 (khalf 0/1), m2/m3 = n-subtile 1
    const uint32_t b_off = (uint32_t)(lane & 7) * A_STRIDE + (uint32_t)((lane >> 3) & 1) * 16u
                           + (uint32_t)(lane >> 4) * 8u * A_STRIDE;

    float acc[8][4];
    #pragma unroll
    for (int nt = 0; nt < 8; ++nt)
        #pragma unroll
        for (int j = 0; j < 4; ++j) acc[nt][j] = 0.f;

    // ---- W cp.async staging helper (per-k tile: 512 uint4 hi + 512 uint4 lo) ----
    const uint4* gw_h = (const uint4*)g_wt_hi + (size_t)PASS * KSZ * 512;
    const uint4* gw_l = (const uint4*)g_wt_lo + (size_t)PASS * KSZ * 512;
    auto stage_w = [&](int k) {
        uint32_t wb = base + SM_W + (uint32_t)(k & 1) * (uint32_t)W_BUF_BYTES;
        #pragma unroll
        for (int i = 0; i < 2; ++i) {
            int j = tid + i * 256;
            uint32_t dst = (uint32_t)(j >> 3) * A_STRIDE + (uint32_t)(j & 7) * 16u;
            cp_async16(wb + dst, gw_h + (size_t)k * 512 + j);
            cp_async16(wb + 9216u + dst, gw_l + (size_t)k * 512 + j);
        }
        cp_commit();
    };

    // ---- prologue: stage W[0], prefetch gather k=0, idx for k=1 ----
    stage_w(0);
    float pf[32];
    {
        int sr0 = gvalid ? nbr[rowg * KSZ + 0] : -1;
        if (sr0 >= 0) {
            const float4* p4 = (const float4*)(src + (size_t)sr0 * C + ghalf * 32);
            #pragma unroll
            for (int q = 0; q < 8; ++q) {
                float4 u = p4[q];
                pf[4 * q + 0] = u.x; pf[4 * q + 1] = u.y;
                pf[4 * q + 2] = u.z; pf[4 * q + 3] = u.w;
            }
        } else {
            #pragma unroll
            for (int j = 0; j < 32; ++j) pf[j] = 0.f;
        }
    }
    int idx_next = (gvalid && 1 < KSZ) ? nbr[rowg * KSZ + 1] : -1;

    for (int k = 0; k < KSZ; ++k) {
        cp_wait0();
        __syncthreads();   // MMA k-1 done (A free) + W[k] visible to all

        // commit A tile for this k from prefetched regs (BN1+ReLU on PASS 1, bf16 split)
        {
            float f[32];
            #pragma unroll
            for (int j = 0; j < 32; ++j) f[j] = pf[j];
            if (PASS == 1) {
                #pragma unroll
                for (int j = 0; j < 32; ++j) {
                    int ch = ghalf * 32 + j;
                    f[j] = fmaxf(fmaf(f[j], s_scale[ch], s_shift[ch]), 0.f);
                }
            }
            #pragma unroll
            for (int s = 0; s < 4; ++s) {
                uint32_t h[4], l[4];
                #pragma unroll
                for (int j = 0; j < 4; ++j) {
                    float x0 = f[s * 8 + 2 * j], x1 = f[s * 8 + 2 * j + 1];
                    h[j] = pack_bf16(x1, x0);
                    float h0 = __uint_as_float(h[j] << 16);
                    float h1 = __uint_as_float(h[j] & 0xffff0000u);
                    l[j] = pack_bf16(x1 - h1, x0 - h0);
                }
                sts128(a_st_h + s * 16u, make_uint4(h[0], h[1], h[2], h[3]));
                sts128(a_st_l + s * 16u, make_uint4(l[0], l[1], l[2], l[3]));
            }
        }
        // kick W[k+1] copy (lands during MMA k)
        if (k + 1 < KSZ) stage_w(k + 1);
        __syncthreads();   // A visible

        // prefetch gather for k+1 (drains during MMA below)
        if (k + 1 < KSZ) {
            int sr = idx_next;
            if (sr >= 0) {
                const float4* p4 = (const float4*)(src + (size_t)sr * C + ghalf * 32);
                #pragma unroll
                for (int q = 0; q < 8; ++q) {
                    float4 u = p4[q];
                    pf[4 * q + 0] = u.x; pf[4 * q + 1] = u.y;
                    pf[4 * q + 2] = u.z; pf[4 * q + 3] = u.w;
                }
            } else {
                #pragma unroll
                for (int j = 0; j < 32; ++j) pf[j] = 0.f;
            }
            idx_next = (gvalid && k + 2 < KSZ) ? nbr[rowg * KSZ + (k + 2)] : -1;
        }

        // 128x64x64 via m16n8k16, 3-term bf16 split
        const uint32_t Wb = base + SM_W + (uint32_t)(k & 1) * (uint32_t)W_BUF_BYTES;
        #pragma unroll
        for (int kk = 0; kk < 4; ++kk) {
            uint32_t ah[4], al[4];
            ldm4(ah, a_ld_h + kk * 32u);
            ldm4(al, a_ld_l + kk * 32u);
            #pragma unroll
            for (int p = 0; p < 4; ++p) {
                uint32_t bh[4], bl[4];
                uint32_t off = b_off + (uint32_t)p * (16u * A_STRIDE) + (uint32_t)kk * 32u;
                ldm4(bh, Wb + off);
                ldm4(bl, Wb + 9216u + off);
                mma_bf16(acc[2 * p],     ah, bh);
                mma_bf16(acc[2 * p],     ah, bl);
                mma_bf16(acc[2 * p],     al, bh);
                mma_bf16(acc[2 * p + 1], ah, bh + 2);
                mma_bf16(acc[2 * p + 1], ah, bl + 2);
                mma_bf16(acc[2 * p + 1], al, bh + 2);
            }
        }
    }

    // ---------------- epilogue ----------------
    const int g = lane >> 2, tig = lane & 3;
    const long row0 = (long)blockIdx.x * TM + w * 16 + g;
    const long row1 = row0 + 8;
    const bool v0 = row0 < (long)n, v1 = row1 < (long)n;

    #pragma unroll
    for (int nt = 0; nt < 8; ++nt) {
        int col = nt * 8 + tig * 2;
        float b0 = s_bias[col], b1 = s_bias[col + 1];
        float y00 = v0 ? acc[nt][0] + b0 : 0.f;
        float y01 = v0 ? acc[nt][1] + b1 : 0.f;
        float y10 = v1 ? acc[nt][2] + b0 : 0.f;
        float y11 = v1 ? acc[nt][3] + b1 : 0.f;
        if (v0) *(float2*)(yout + (size_t)row0 * C + col) = make_float2(y00, y01);
        if (v1) *(float2*)(yout + (size_t)row1 * C + col) = make_float2(y10, y11);
        float sv0 = y00 + y10, sv1 = y01 + y11;
        float sq0 = y00 * y00 + y10 * y10, sq1 = y01 * y01 + y11 * y11;
        #pragma unroll
        for (int o = 16; o >= 4; o >>= 1) {
            sv0 += __shfl_xor_sync(0xffffffffu, sv0, o);
            sv1 += __shfl_xor_sync(0xffffffffu, sv1, o);
            sq0 += __shfl_xor_sync(0xffffffffu, sq0, o);
            sq1 += __shfl_xor_sync(0xffffffffu, sq1, o);
        }
        if (lane < 4) {
            atomicAdd(&s_sum[col], sv0); atomicAdd(&s_sum[col + 1], sv1);
            atomicAdd(&s_sq[col],  sq0); atomicAdd(&s_sq[col + 1],  sq1);
        }
    }
    __syncthreads();
    if (tid < C) { atomicAdd(&gsum[tid], s_sum[tid]); atomicAdd(&gsq[tid], s_sq[tid]); }
}

template<int PASS>
__global__ void stats_kernel(const float* __restrict__ gamma,
                             const float* __restrict__ beta, int n) {
    int d = threadIdx.x;
    if (d >= C) return;
    float sum = (PASS == 0) ? g_sum1[d] : g_sum2[d];
    float sq  = (PASS == 0) ? g_sq1[d]  : g_sq2[d];
    float inv_n = 1.0f / (float)n;
    float mean = sum * inv_n;
    float var = fmaxf(sq * inv_n - mean * mean, 0.f);
    float sc = gamma[d] * rsqrtf(var + EPSV);
    float sh = beta[d] - mean * sc;
    if (PASS == 0) { g_scale1[d] = sc; g_shift1[d] = sh; }
    else           { g_scale2[d] = sc; g_shift2[d] = sh; }
}

__global__ void final_kernel(const float* __restrict__ feats,
                             float* __restrict__ out, int n) {
    int i = blockIdx.x * blockDim.x + threadIdx.x;
    int total = n * (C / 4);
    if (i >= total) return;
    int c = (i & 15) * 4;
    float4 y = ((const float4*)out)[i];
    float4 f = ((const float4*)feats)[i];
    float4 r;
    r.x = fmaxf(fmaf(y.x, g_scale2[c + 0], g_shift2[c + 0]) + f.x, 0.f);
    r.y = fmaxf(fmaf(y.y, g_scale2[c + 1], g_shift2[c + 1]) + f.y, 0.f);
    r.z = fmaxf(fmaf(y.z, g_scale2[c + 2], g_shift2[c + 2]) + f.z, 0.f);
    r.w = fmaxf(fmaf(y.w, g_scale2[c + 3], g_shift2[c + 3]) + f.w, 0.f);
    ((float4*)out)[i] = r;
}

extern "C" void kernel_launch(void* const* d_in, const int* in_sizes, int n_in,
                              void* d_out, int out_size) {
    const float* feats = (const float*)d_in[0];
    const int*   nbr   = (const int*)d_in[1];
    const float* W1    = (const float*)d_in[2];
    const float* b1    = (const float*)d_in[3];
    const float* g1    = (const float*)d_in[4];
    const float* be1   = (const float*)d_in[5];
    const float* W2    = (const float*)d_in[6];
    const float* b2    = (const float*)d_in[7];
    const float* g2    = (const float*)d_in[8];
    const float* be2   = (const float*)d_in[9];
    float* out = (float*)d_out;

    int n = in_sizes[0] / C;
    int conv_blocks = (n + TM - 1) / TM;
    int ew_blocks = (n * (C / 4) + 255) / 256;

    cudaFuncSetAttribute(conv_mma_kernel<0>, cudaFuncAttributeMaxDynamicSharedMemorySize, SMEM_DYN);
    cudaFuncSetAttribute(conv_mma_kernel<1>, cudaFuncAttributeMaxDynamicSharedMemorySize, SMEM_DYN);

    zero_stats_kernel<<<1, 64>>>();
    prep_w_kernel<<<2 * KSZ, 256>>>(W1, W2);
    conv_mma_kernel<0><<<conv_blocks, 256, SMEM_DYN>>>(feats, nbr, b1, nullptr, n);
    stats_kernel<0><<<1, 64>>>(g1, be1, n);
    conv_mma_kernel<1><<<conv_blocks, 256, SMEM_DYN>>>(feats, nbr, b2, out, n);
    stats_kernel<1><<<1, 64>>>(g2, be2, n);
    final_kernel<<<ew_blocks, 256>>>(feats, out, n);
}

// round 6
// speedup vs baseline: 3.0093x; 1.8803x over previous
#include <cuda_runtime.h>
#include <cstdint>

#define C 64
#define KSZ 27
#define TM 128
#define NMAX 100000
#define EPSV 1e-5f

// SMEM: A stages (hi 16K + lo 16K) x2, then W stages (hi 8K + lo 8K) x2
#define SM_A 0
#define A_STAGE 32768
#define SM_W 65536
#define W_STAGE 16384
#define SMEM_DYN (65536 + 32768 + 1024)

// Device scratch (no allocation allowed)
__device__ float g_y1[NMAX * C];
__device__ float g_sum1[C], g_sq1[C], g_sum2[C], g_sq2[C];
__device__ float g_scale1[C], g_shift1[C], g_scale2[C], g_shift2[C];
// pre-split activations (bf16 hi/lo), 128B rows
__device__ __align__(16) unsigned short g_a_hi[NMAX * C];
__device__ __align__(16) unsigned short g_a_lo[NMAX * C];
// weights [conv][k][d][c] bf16 hi/lo, PRE-SWIZZLED (SW128) for linear smem copy
__device__ __align__(16) unsigned short g_wt_hi[2 * KSZ * C * C];
__device__ __align__(16) unsigned short g_wt_lo[2 * KSZ * C * C];

// ---------------- helpers ----------------
static __device__ __forceinline__ uint32_t smem_u32(const void* p) {
    uint32_t a;
    asm("{ .reg .u64 t; cvta.to.shared.u64 t, %1; cvt.u32.u64 %0, t; }" : "=r"(a) : "l"(p));
    return a;
}
static __device__ __forceinline__ uint32_t pack_bf16(float up, float lo) {
    uint32_t r;
    asm("cvt.rn.bf16x2.f32 %0, %1, %2;" : "=r"(r) : "f"(up), "f"(lo));
    return r;
}
static __device__ __forceinline__ void cp_async16(uint32_t dst, const void* src) {
    asm volatile("cp.async.cg.shared.global [%0], [%1], 16;"
                 :: "r"(dst), "l"(__cvta_generic_to_global(src)) : "memory");
}
static __device__ __forceinline__ void cp_commit() {
    asm volatile("cp.async.commit_group;" ::: "memory");
}
static __device__ __forceinline__ void cp_wait0() {
    asm volatile("cp.async.wait_group 0;" ::: "memory");
}
static __device__ __forceinline__ void ldm4(uint32_t* r, uint32_t addr) {
    asm volatile("ldmatrix.sync.aligned.m8n8.x4.shared.b16 {%0,%1,%2,%3}, [%4];"
                 : "=r"(r[0]), "=r"(r[1]), "=r"(r[2]), "=r"(r[3]) : "r"(addr));
}
static __device__ __forceinline__ void mma_bf16(float* c, const uint32_t* a, const uint32_t* b) {
    asm volatile(
        "mma.sync.aligned.m16n8k16.row.col.f32.bf16.bf16.f32 "
        "{%0,%1,%2,%3}, {%4,%5,%6,%7}, {%8,%9}, {%0,%1,%2,%3};"
        : "+f"(c[0]), "+f"(c[1]), "+f"(c[2]), "+f"(c[3])
        : "r"(a[0]), "r"(a[1]), "r"(a[2]), "r"(a[3]), "r"(b[0]), "r"(b[1]));
}
static __device__ __forceinline__ void split2(float x0, float x1, uint32_t& h, uint32_t& l) {
    h = pack_bf16(x1, x0);
    float h0 = __uint_as_float(h << 16);
    float h1 = __uint_as_float(h & 0xffff0000u);
    l = pack_bf16(x1 - h1, x0 - h0);
}

// ---------------- small kernels ----------------
__global__ void zero_stats_kernel() {
    int t = threadIdx.x;
    if (t < C) { g_sum1[t] = 0.f; g_sq1[t] = 0.f; g_sum2[t] = 0.f; g_sq2[t] = 0.f; }
}

// weights: logical [k][d][c] -> pre-swizzled SW128 rows (row=d, 128B)
__global__ void prep_w_kernel(const float* __restrict__ W1, const float* __restrict__ W2) {
    int b = blockIdx.x;             // 0..2*KSZ-1
    int conv = b / KSZ, k = b % KSZ;
    const float* W = (conv == 0) ? W1 : W2;
    for (int i = threadIdx.x; i < C * C; i += blockDim.x) {
        int c = i >> 6, d = i & 63;
        float v = W[k * C * C + c * C + d];
        uint32_t hb = pack_bf16(0.f, v) & 0xffffu;
        float hf = __uint_as_float(hb << 16);
        uint32_t lb = pack_bf16(0.f, v - hf) & 0xffffu;
        uint32_t sseg = (uint32_t)((c >> 3) ^ (d & 7));
        uint32_t idx = (uint32_t)(conv * KSZ + k) * 4096u
                     + (uint32_t)d * 64u + sseg * 8u + (uint32_t)(c & 7);
        g_wt_hi[idx] = (unsigned short)hb;
        g_wt_lo[idx] = (unsigned short)lb;
    }
}

// feats f32 -> bf16 hi/lo split (no transform)
__global__ void split_feats_kernel(const float* __restrict__ feats, int n) {
    int i = blockIdx.x * blockDim.x + threadIdx.x;     // float4 index
    int total = n * (C / 4);
    if (i >= total) return;
    float4 v = ((const float4*)feats)[i];
    uint32_t h0, l0, h1, l1;
    split2(v.x, v.y, h0, l0);
    split2(v.z, v.w, h1, l1);
    ((uint2*)g_a_hi)[i] = make_uint2(h0, h1);
    ((uint2*)g_a_lo)[i] = make_uint2(l0, l1);
}

// y1 f32 -> BN1+ReLU -> bf16 hi/lo split (overwrites g_a_hi/lo)
__global__ void split_y1_kernel(int n) {
    int i = blockIdx.x * blockDim.x + threadIdx.x;
    int total = n * (C / 4);
    if (i >= total) return;
    int c = (i & 15) * 4;
    float4 v = ((const float4*)g_y1)[i];
    v.x = fmaxf(fmaf(v.x, g_scale1[c + 0], g_shift1[c + 0]), 0.f);
    v.y = fmaxf(fmaf(v.y, g_scale1[c + 1], g_shift1[c + 1]), 0.f);
    v.z = fmaxf(fmaf(v.z, g_scale1[c + 2], g_shift1[c + 2]), 0.f);
    v.w = fmaxf(fmaf(v.w, g_scale1[c + 3], g_shift1[c + 3]), 0.f);
    uint32_t h0, l0, h1, l1;
    split2(v.x, v.y, h0, l0);
    split2(v.z, v.w, h1, l1);
    ((uint2*)g_a_hi)[i] = make_uint2(h0, h1);
    ((uint2*)g_a_lo)[i] = make_uint2(l0, l1);
}

// ---------------- main conv (pure cp.async + ldmatrix + MMA) ----------------
template<int PASS>
__global__ __launch_bounds__(256, 2) void conv_mma_kernel(
    const int* __restrict__ nbr, const float* __restrict__ bias,
    float* __restrict__ dout, int n)
{
    extern __shared__ char dsm[];
    __shared__ float s_sum[C], s_sq[C], s_bias[C];

    float*       yout = (PASS == 0) ? g_y1   : dout;
    float*       gsum = (PASS == 0) ? g_sum1 : g_sum2;
    float*       gsq  = (PASS == 0) ? g_sq1  : g_sq2;

    const int tid = threadIdx.x, lane = tid & 31, w = tid >> 5;
    const uint32_t base = (smem_u32(dsm) + 1023u) & ~1023u;

    if (tid < C) { s_sum[tid] = 0.f; s_sq[tid] = 0.f; s_bias[tid] = bias[tid]; }

    // ---- copy-role mapping: seg s = tid&7, rows r0+32i ----
    const int cseg = tid & 7;
    const int crow = tid >> 3;                 // 0..31
    const long blk0 = (long)blockIdx.x * TM;

    // W chunks: j = tid, tid+256 (512 x 16B per buf)
    const uint4* gw_h = (const uint4*)g_wt_hi + (size_t)PASS * KSZ * 512;
    const uint4* gw_l = (const uint4*)g_wt_lo + (size_t)PASS * KSZ * 512;

    // issue one full stage (A gather + W) for kernel-offset k into stage s
    int pidx[4];
    auto load_idx = [&](int k) {
        #pragma unroll
        for (int i = 0; i < 4; ++i) {
            long r = blk0 + crow + 32 * i;
            pidx[i] = (r < (long)n) ? nbr[r * KSZ + k] : 0;
        }
    };
    auto issue_stage = [&](int k) {
        const int s = k & 1;
        const uint32_t Ah = base + SM_A + (uint32_t)s * A_STAGE;
        const uint32_t Al = Ah + 16384u;
        const uint32_t Wh = base + SM_W + (uint32_t)s * W_STAGE;
        const uint32_t Wl = Wh + 8192u;
        #pragma unroll
        for (int i = 0; i < 4; ++i) {
            int r = crow + 32 * i;
            uint32_t dst = (uint32_t)r * 128u + (uint32_t)((cseg ^ (r & 7)) << 4);
            size_t srcoff = (size_t)pidx[i] * 64 + cseg * 8;
            cp_async16(Ah + dst, g_a_hi + srcoff);
            cp_async16(Al + dst, g_a_lo + srcoff);
        }
        #pragma unroll
        for (int i = 0; i < 2; ++i) {
            int j = tid + i * 256;
            cp_async16(Wh + (uint32_t)j * 16u, gw_h + (size_t)k * 512 + j);
            cp_async16(Wl + (uint32_t)j * 16u, gw_l + (size_t)k * 512 + j);
        }
        cp_commit();
    };

    // ---- mma-role addressing ----
    const int ar = w * 16 + (lane & 15);           // A row
    const int ahalf = lane >> 4;                   // k half (16B)
    const uint32_t a_row_off = (uint32_t)ar * 128u;
    const int ax7 = ar & 7;
    const int bd = ((lane >> 4) & 1) * 8 + (lane & 7);   // B row base (within 16)
    const int bkh = (lane >> 3) & 1;
    const int bx7 = bd & 7;

    float acc[8][4];
    #pragma unroll
    for (int nt = 0; nt < 8; ++nt)
        #pragma unroll
        for (int j = 0; j < 4; ++j) acc[nt][j] = 0.f;

    // ---- prologue ----
    load_idx(0);
    issue_stage(0);
    load_idx(1);

    for (int k = 0; k < KSZ; ++k) {
        cp_wait0();
        __syncthreads();          // stage k ready; all warps done with stage k-1 MMA

        if (k + 1 < KSZ) {
            issue_stage(k + 1);   // writes the other stage
            if (k + 2 < KSZ) load_idx(k + 2);
        }

        const int s = k & 1;
        const uint32_t Ah = base + SM_A + (uint32_t)s * A_STAGE;
        const uint32_t Al = Ah + 16384u;
        const uint32_t Wh = base + SM_W + (uint32_t)s * W_STAGE;
        const uint32_t Wl = Wh + 8192u;

        #pragma unroll
        for (int kk = 0; kk < 4; ++kk) {
            uint32_t ah[4], al[4];
            uint32_t aoff = a_row_off + (uint32_t)(((kk * 2 + ahalf) ^ ax7) << 4);
            ldm4(ah, Ah + aoff);
            ldm4(al, Al + aoff);
            uint32_t bseg = (uint32_t)(((kk * 2 + bkh) ^ bx7) << 4);
            #pragma unroll
            for (int p = 0; p < 4; ++p) {
                uint32_t bh[4], bl[4];
                uint32_t boff = (uint32_t)(p * 16 + bd) * 128u + bseg;
                ldm4(bh, Wh + boff);
                ldm4(bl, Wl + boff);
                mma_bf16(acc[2 * p],     ah, bh);
                mma_bf16(acc[2 * p],     ah, bl);
                mma_bf16(acc[2 * p],     al, bh);
                mma_bf16(acc[2 * p + 1], ah, bh + 2);
                mma_bf16(acc[2 * p + 1], ah, bl + 2);
                mma_bf16(acc[2 * p + 1], al, bh + 2);
            }
        }
    }

    // ---------------- epilogue ----------------
    const int g = lane >> 2, tig = lane & 3;
    const long row0 = blk0 + w * 16 + g;
    const long row1 = row0 + 8;
    const bool v0 = row0 < (long)n, v1 = row1 < (long)n;

    #pragma unroll
    for (int nt = 0; nt < 8; ++nt) {
        int col = nt * 8 + tig * 2;
        float b0 = s_bias[col], b1 = s_bias[col + 1];
        float y00 = v0 ? acc[nt][0] + b0 : 0.f;
        float y01 = v0 ? acc[nt][1] + b1 : 0.f;
        float y10 = v1 ? acc[nt][2] + b0 : 0.f;
        float y11 = v1 ? acc[nt][3] + b1 : 0.f;
        if (v0) *(float2*)(yout + (size_t)row0 * C + col) = make_float2(y00, y01);
        if (v1) *(float2*)(yout + (size_t)row1 * C + col) = make_float2(y10, y11);
        float sv0 = y00 + y10, sv1 = y01 + y11;
        float sq0 = y00 * y00 + y10 * y10, sq1 = y01 * y01 + y11 * y11;
        #pragma unroll
        for (int o = 16; o >= 4; o >>= 1) {
            sv0 += __shfl_xor_sync(0xffffffffu, sv0, o);
            sv1 += __shfl_xor_sync(0xffffffffu, sv1, o);
            sq0 += __shfl_xor_sync(0xffffffffu, sq0, o);
            sq1 += __shfl_xor_sync(0xffffffffu, sq1, o);
        }
        if (lane < 4) {
            atomicAdd(&s_sum[col], sv0); atomicAdd(&s_sum[col + 1], sv1);
            atomicAdd(&s_sq[col],  sq0); atomicAdd(&s_sq[col + 1],  sq1);
        }
    }
    __syncthreads();
    if (tid < C) { atomicAdd(&gsum[tid], s_sum[tid]); atomicAdd(&gsq[tid], s_sq[tid]); }
}

template<int PASS>
__global__ void stats_kernel(const float* __restrict__ gamma,
                             const float* __restrict__ beta, int n) {
    int d = threadIdx.x;
    if (d >= C) return;
    float sum = (PASS == 0) ? g_sum1[d] : g_sum2[d];
    float sq  = (PASS == 0) ? g_sq1[d]  : g_sq2[d];
    float inv_n = 1.0f / (float)n;
    float mean = sum * inv_n;
    float var = fmaxf(sq * inv_n - mean * mean, 0.f);
    float sc = gamma[d] * rsqrtf(var + EPSV);
    float sh = beta[d] - mean * sc;
    if (PASS == 0) { g_scale1[d] = sc; g_shift1[d] = sh; }
    else           { g_scale2[d] = sc; g_shift2[d] = sh; }
}

__global__ void final_kernel(const float* __restrict__ feats,
                             float* __restrict__ out, int n) {
    int i = blockIdx.x * blockDim.x + threadIdx.x;
    int total = n * (C / 4);
    if (i >= total) return;
    int c = (i & 15) * 4;
    float4 y = ((const float4*)out)[i];
    float4 f = ((const float4*)feats)[i];
    float4 r;
    r.x = fmaxf(fmaf(y.x, g_scale2[c + 0], g_shift2[c + 0]) + f.x, 0.f);
    r.y = fmaxf(fmaf(y.y, g_scale2[c + 1], g_shift2[c + 1]) + f.y, 0.f);
    r.z = fmaxf(fmaf(y.z, g_scale2[c + 2], g_shift2[c + 2]) + f.z, 0.f);
    r.w = fmaxf(fmaf(y.w, g_scale2[c + 3], g_shift2[c + 3]) + f.w, 0.f);
    ((float4*)out)[i] = r;
}

extern "C" void kernel_launch(void* const* d_in, const int* in_sizes, int n_in,
                              void* d_out, int out_size) {
    const float* feats = (const float*)d_in[0];
    const int*   nbr   = (const int*)d_in[1];
    const float* W1    = (const float*)d_in[2];
    const float* b1    = (const float*)d_in[3];
    const float* g1    = (const float*)d_in[4];
    const float* be1   = (const float*)d_in[5];
    const float* W2    = (const float*)d_in[6];
    const float* b2    = (const float*)d_in[7];
    const float* g2    = (const float*)d_in[8];
    const float* be2   = (const float*)d_in[9];
    float* out = (float*)d_out;

    int n = in_sizes[0] / C;
    int conv_blocks = (n + TM - 1) / TM;
    int ew_blocks = (n * (C / 4) + 255) / 256;

    cudaFuncSetAttribute(conv_mma_kernel<0>, cudaFuncAttributeMaxDynamicSharedMemorySize, SMEM_DYN);
    cudaFuncSetAttribute(conv_mma_kernel<1>, cudaFuncAttributeMaxDynamicSharedMemorySize, SMEM_DYN);

    zero_stats_kernel<<<1, 64>>>();
    prep_w_kernel<<<2 * KSZ, 256>>>(W1, W2);
    split_feats_kernel<<<ew_blocks, 256>>>(feats, n);
    conv_mma_kernel<0><<<conv_blocks, 256, SMEM_DYN>>>(nbr, b1, nullptr, n);
    stats_kernel<0><<<1, 64>>>(g1, be1, n);
    split_y1_kernel<<<ew_blocks, 256>>>(n);
    conv_mma_kernel<1><<<conv_blocks, 256, SMEM_DYN>>>(nbr, b2, out, n);
    stats_kernel<1><<<1, 64>>>(g2, be2, n);
    final_kernel<<<ew_blocks, 256>>>(feats, out, n);
}

// round 7
// speedup vs baseline: 3.3526x; 1.1141x over previous
#include <cuda_runtime.h>
#include <cstdint>

#define C 64
#define KSZ 27
#define TM 128
#define NMAX 100000
#define EPSV 1e-5f

// SMEM: A stages (32KB fp32) x2, W stages (16KB fp32) x2
#define SM_A 0
#define A_STAGE 32768
#define SM_W 65536
#define W_STAGE 16384
#define SMEM_DYN (65536 + 32768 + 1024)

// Device scratch (no allocation allowed)
__device__ float g_y1[NMAX * C];
__device__ float g_sum1[C], g_sq1[C], g_sum2[C], g_sq2[C];
__device__ float g_scale1[C], g_shift1[C], g_scale2[C], g_shift2[C];
// tf32-rounded activations, row-major [n][64] fp32 (256B rows)
__device__ __align__(16) float g_a[NMAX * C];
// weights [conv][k][d][c] fp32 tf32-rounded, PRE-SWIZZLED for linear smem copy
__device__ __align__(16) float g_wt[2 * KSZ * C * C];

// ---------------- helpers ----------------
static __device__ __forceinline__ uint32_t smem_u32(const void* p) {
    uint32_t a;
    asm("{ .reg .u64 t; cvta.to.shared.u64 t, %1; cvt.u32.u64 %0, t; }" : "=r"(a) : "l"(p));
    return a;
}
static __device__ __forceinline__ float tf32r(float x) {
    uint32_t r;
    asm("cvt.rna.tf32.f32 %0, %1;" : "=r"(r) : "f"(x));
    return __uint_as_float(r);
}
static __device__ __forceinline__ void cp_async16(uint32_t dst, const void* src) {
    asm volatile("cp.async.cg.shared.global [%0], [%1], 16;"
                 :: "r"(dst), "l"(__cvta_generic_to_global(src)) : "memory");
}
static __device__ __forceinline__ void cp_commit() {
    asm volatile("cp.async.commit_group;" ::: "memory");
}
static __device__ __forceinline__ void cp_wait0() {
    asm volatile("cp.async.wait_group 0;" ::: "memory");
}
static __device__ __forceinline__ void ldm4(uint32_t* r, uint32_t addr) {
    asm volatile("ldmatrix.sync.aligned.m8n8.x4.shared.b16 {%0,%1,%2,%3}, [%4];"
                 : "=r"(r[0]), "=r"(r[1]), "=r"(r[2]), "=r"(r[3]) : "r"(addr));
}
static __device__ __forceinline__ void mma_tf32(float* c, const uint32_t* a, const uint32_t* b) {
    asm volatile(
        "mma.sync.aligned.m16n8k8.row.col.f32.tf32.tf32.f32 "
        "{%0,%1,%2,%3}, {%4,%5,%6,%7}, {%8,%9}, {%0,%1,%2,%3};"
        : "+f"(c[0]), "+f"(c[1]), "+f"(c[2]), "+f"(c[3])
        : "r"(a[0]), "r"(a[1]), "r"(a[2]), "r"(a[3]), "r"(b[0]), "r"(b[1]));
}

// ---------------- small kernels ----------------
__global__ void zero_stats_kernel() {
    int t = threadIdx.x;
    if (t < C) { g_sum1[t] = 0.f; g_sq1[t] = 0.f; g_sum2[t] = 0.f; g_sq2[t] = 0.f; }
}

// weights: logical [k][c][d] -> [conv][k][d][c] fp32 tf32-rounded, pre-swizzled rows
// row = d (256B = 16 segs of 16B); seg s stored at (s ^ (d&7))
__global__ void prep_w_kernel(const float* __restrict__ W1, const float* __restrict__ W2) {
    int b = blockIdx.x;             // 0..2*KSZ-1
    int conv = b / KSZ, k = b % KSZ;
    const float* W = (conv == 0) ? W1 : W2;
    for (int i = threadIdx.x; i < C * C; i += blockDim.x) {
        int c = i >> 6, d = i & 63;
        float v = tf32r(W[k * C * C + c * C + d]);
        uint32_t seg = (uint32_t)(c >> 2);
        uint32_t idx = (uint32_t)(conv * KSZ + k) * 4096u + (uint32_t)d * 64u
                     + ((seg ^ (uint32_t)(d & 7)) << 2) + (uint32_t)(c & 3);
        g_wt[idx] = v;
    }
}

// feats -> tf32-rounded copy
__global__ void prep_feats_kernel(const float* __restrict__ feats, int n) {
    int i = blockIdx.x * blockDim.x + threadIdx.x;     // float4 index
    int total = n * (C / 4);
    if (i >= total) return;
    float4 v = ((const float4*)feats)[i];
    v.x = tf32r(v.x); v.y = tf32r(v.y); v.z = tf32r(v.z); v.w = tf32r(v.w);
    ((float4*)g_a)[i] = v;
}

// y1 -> BN1+ReLU -> tf32 round (overwrites g_a)
__global__ void prep_h1_kernel(int n) {
    int i = blockIdx.x * blockDim.x + threadIdx.x;
    int total = n * (C / 4);
    if (i >= total) return;
    int c = (i & 15) * 4;
    float4 v = ((const float4*)g_y1)[i];
    v.x = tf32r(fmaxf(fmaf(v.x, g_scale1[c + 0], g_shift1[c + 0]), 0.f));
    v.y = tf32r(fmaxf(fmaf(v.y, g_scale1[c + 1], g_shift1[c + 1]), 0.f));
    v.z = tf32r(fmaxf(fmaf(v.z, g_scale1[c + 2], g_shift1[c + 2]), 0.f));
    v.w = tf32r(fmaxf(fmaf(v.w, g_scale1[c + 3], g_shift1[c + 3]), 0.f));
    ((float4*)g_a)[i] = v;
}

// ---------------- main conv (cp.async + ldmatrix + tf32 MMA) ----------------
template<int PASS>
__global__ __launch_bounds__(256, 2) void conv_mma_kernel(
    const int* __restrict__ nbr, const float* __restrict__ bias,
    float* __restrict__ dout, int n)
{
    extern __shared__ char dsm[];
    __shared__ float s_sum[C], s_sq[C], s_bias[C];

    float*       yout = (PASS == 0) ? g_y1   : dout;
    float*       gsum = (PASS == 0) ? g_sum1 : g_sum2;
    float*       gsq  = (PASS == 0) ? g_sq1  : g_sq2;

    const int tid = threadIdx.x, lane = tid & 31, w = tid >> 5;
    const uint32_t base = (smem_u32(dsm) + 1023u) & ~1023u;

    if (tid < C) { s_sum[tid] = 0.f; s_sq[tid] = 0.f; s_bias[tid] = bias[tid]; }

    // ---- copy-role mapping: 16 segs per 256B row ----
    const int cseg = tid & 15;
    const int crow = tid >> 4;                 // 0..15, rows crow + 16i
    const long blk0 = (long)blockIdx.x * TM;

    const uint4* gw = (const uint4*)g_wt + (size_t)PASS * KSZ * 1024;

    int pidx[8];
    auto load_idx = [&](int k) {
        #pragma unroll
        for (int i = 0; i < 8; ++i) {
            long r = blk0 + crow + 16 * i;
            pidx[i] = (r < (long)n) ? nbr[r * KSZ + k] : 0;
        }
    };
    auto issue_stage = [&](int k) {
        const int s = k & 1;
        const uint32_t Ast = base + SM_A + (uint32_t)s * A_STAGE;
        const uint32_t Wst = base + SM_W + (uint32_t)s * W_STAGE;
        #pragma unroll
        for (int i = 0; i < 8; ++i) {
            int r = crow + 16 * i;
            uint32_t dst = (uint32_t)r * 256u + (uint32_t)((cseg ^ (r & 7)) << 4);
            cp_async16(Ast + dst, g_a + (size_t)pidx[i] * 64 + cseg * 4);
        }
        #pragma unroll
        for (int i = 0; i < 4; ++i) {
            int j = tid + i * 256;
            cp_async16(Wst + (uint32_t)j * 16u, gw + (size_t)k * 1024 + j);
        }
        cp_commit();
    };

    // ---- mma-role addressing ----
    // A ldm4 tiles: lanes0-7 rows0-7/k-lo, 8-15 rows8-15/k-lo, 16-23 rows0-7/k-hi, 24-31 rows8-15/k-hi
    const int arow = w * 16 + (lane & 7) + 8 * ((lane >> 3) & 1);
    const uint32_t a_row_off = (uint32_t)arow * 256u;
    const int ax7 = arow & 7;
    const int akh = lane >> 4;                   // k-seg half (0/1)
    // B ldm4 tiles: which = lane>>3: (n-sub, k-half) = (which>>1, which&1)
    const int bwhich = lane >> 3;
    const int bnrow_loc = ((bwhich >> 1) << 3) + (lane & 7);   // 0..15 within p-pair
    const int bkh = bwhich & 1;

    float acc[8][4];
    #pragma unroll
    for (int nt = 0; nt < 8; ++nt)
        #pragma unroll
        for (int j = 0; j < 4; ++j) acc[nt][j] = 0.f;

    // ---- prologue ----
    load_idx(0);
    issue_stage(0);
    load_idx(1);

    for (int k = 0; k < KSZ; ++k) {
        cp_wait0();
        __syncthreads();          // stage k ready; all warps done with stage k-1

        if (k + 1 < KSZ) {
            issue_stage(k + 1);
            if (k + 2 < KSZ) load_idx(k + 2);
        }

        const int s = k & 1;
        const uint32_t Ast = base + SM_A + (uint32_t)s * A_STAGE;
        const uint32_t Wst = base + SM_W + (uint32_t)s * W_STAGE;

        #pragma unroll
        for (int kk = 0; kk < 8; ++kk) {
            uint32_t a[4];
            ldm4(a, Ast + a_row_off + (uint32_t)(((2 * kk + akh) ^ ax7) << 4));
            #pragma unroll
            for (int pp = 0; pp < 4; ++pp) {
                uint32_t b[4];
                int nrow = pp * 16 + bnrow_loc;
                ldm4(b, Wst + (uint32_t)nrow * 256u
                          + (uint32_t)(((2 * kk + bkh) ^ (nrow & 7)) << 4));
                mma_tf32(acc[2 * pp],     a, b);
                mma_tf32(acc[2 * pp + 1], a, b + 2);
            }
        }
    }

    // ---------------- epilogue ----------------
    const int g = lane >> 2, tig = lane & 3;
    const long row0 = blk0 + w * 16 + g;
    const long row1 = row0 + 8;
    const bool v0 = row0 < (long)n, v1 = row1 < (long)n;

    #pragma unroll
    for (int nt = 0; nt < 8; ++nt) {
        int col = nt * 8 + tig * 2;
        float b0 = s_bias[col], b1 = s_bias[col + 1];
        float y00 = v0 ? acc[nt][0] + b0 : 0.f;
        float y01 = v0 ? acc[nt][1] + b1 : 0.f;
        float y10 = v1 ? acc[nt][2] + b0 : 0.f;
        float y11 = v1 ? acc[nt][3] + b1 : 0.f;
        if (v0) *(float2*)(yout + (size_t)row0 * C + col) = make_float2(y00, y01);
        if (v1) *(float2*)(yout + (size_t)row1 * C + col) = make_float2(y10, y11);
        float sv0 = y00 + y10, sv1 = y01 + y11;
        float sq0 = y00 * y00 + y10 * y10, sq1 = y01 * y01 + y11 * y11;
        #pragma unroll
        for (int o = 16; o >= 4; o >>= 1) {
            sv0 += __shfl_xor_sync(0xffffffffu, sv0, o);
            sv1 += __shfl_xor_sync(0xffffffffu, sv1, o);
            sq0 += __shfl_xor_sync(0xffffffffu, sq0, o);
            sq1 += __shfl_xor_sync(0xffffffffu, sq1, o);
        }
        if (lane < 4) {
            atomicAdd(&s_sum[col], sv0); atomicAdd(&s_sum[col + 1], sv1);
            atomicAdd(&s_sq[col],  sq0); atomicAdd(&s_sq[col + 1],  sq1);
        }
    }
    __syncthreads();
    if (tid < C) { atomicAdd(&gsum[tid], s_sum[tid]); atomicAdd(&gsq[tid], s_sq[tid]); }
}

template<int PASS>
__global__ void stats_kernel(const float* __restrict__ gamma,
                             const float* __restrict__ beta, int n) {
    int d = threadIdx.x;
    if (d >= C) return;
    float sum = (PASS == 0) ? g_sum1[d] : g_sum2[d];
    float sq  = (PASS == 0) ? g_sq1[d]  : g_sq2[d];
    float inv_n = 1.0f / (float)n;
    float mean = sum * inv_n;
    float var = fmaxf(sq * inv_n - mean * mean, 0.f);
    float sc = gamma[d] * rsqrtf(var + EPSV);
    float sh = beta[d] - mean * sc;
    if (PASS == 0) { g_scale1[d] = sc; g_shift1[d] = sh; }
    else           { g_scale2[d] = sc; g_shift2[d] = sh; }
}

__global__ void final_kernel(const float* __restrict__ feats,
                             float* __restrict__ out, int n) {
    int i = blockIdx.x * blockDim.x + threadIdx.x;
    int total = n * (C / 4);
    if (i >= total) return;
    int c = (i & 15) * 4;
    float4 y = ((const float4*)out)[i];
    float4 f = ((const float4*)feats)[i];
    float4 r;
    r.x = fmaxf(fmaf(y.x, g_scale2[c + 0], g_shift2[c + 0]) + f.x, 0.f);
    r.y = fmaxf(fmaf(y.y, g_scale2[c + 1], g_shift2[c + 1]) + f.y, 0.f);
    r.z = fmaxf(fmaf(y.z, g_scale2[c + 2], g_shift2[c + 2]) + f.z, 0.f);
    r.w = fmaxf(fmaf(y.w, g_scale2[c + 3], g_shift2[c + 3]) + f.w, 0.f);
    ((float4*)out)[i] = r;
}

extern "C" void kernel_launch(void* const* d_in, const int* in_sizes, int n_in,
                              void* d_out, int out_size) {
    const float* feats = (const float*)d_in[0];
    const int*   nbr   = (const int*)d_in[1];
    const float* W1    = (const float*)d_in[2];
    const float* b1    = (const float*)d_in[3];
    const float* g1    = (const float*)d_in[4];
    const float* be1   = (const float*)d_in[5];
    const float* W2    = (const float*)d_in[6];
    const float* b2    = (const float*)d_in[7];
    const float* g2    = (const float*)d_in[8];
    const float* be2   = (const float*)d_in[9];
    float* out = (float*)d_out;

    int n = in_sizes[0] / C;
    int conv_blocks = (n + TM - 1) / TM;
    int ew_blocks = (n * (C / 4) + 255) / 256;

    cudaFuncSetAttribute(conv_mma_kernel<0>, cudaFuncAttributeMaxDynamicSharedMemorySize, SMEM_DYN);
    cudaFuncSetAttribute(conv_mma_kernel<1>, cudaFuncAttributeMaxDynamicSharedMemorySize, SMEM_DYN);

    zero_stats_kernel<<<1, 64>>>();
    prep_w_kernel<<<2 * KSZ, 256>>>(W1, W2);
    prep_feats_kernel<<<ew_blocks, 256>>>(feats, n);
    conv_mma_kernel<0><<<conv_blocks, 256, SMEM_DYN>>>(nbr, b1, nullptr, n);
    stats_kernel<0><<<1, 64>>>(g1, be1, n);
    prep_h1_kernel<<<ew_blocks, 256>>>(n);
    conv_mma_kernel<1><<<conv_blocks, 256, SMEM_DYN>>>(nbr, b2, out, n);
    stats_kernel<1><<<1, 64>>>(g2, be2, n);
    final_kernel<<<ew_blocks, 256>>>(feats, out, n);
}

// round 8
// speedup vs baseline: 5.2604x; 1.5690x over previous
#include <cuda_runtime.h>
#include <cuda_fp16.h>
#include <cstdint>

#define C 64
#define KSZ 27
#define TM 128
#define NMAX 100000
#define EPSV 1e-5f

// 3 stages, each: A 16KB + W 8KB
#define STAGE_BYTES 24576
#define SMEM_DYN (3 * STAGE_BYTES + 1024)

// Device scratch (no allocation allowed)
__device__ float g_y1[NMAX * C];
__device__ float g_sum1[C], g_sq1[C], g_sum2[C], g_sq2[C];
__device__ float g_scale1[C], g_shift1[C], g_scale2[C], g_shift2[C];
// fp16 activations, row-major [n][64] (128B rows)
__device__ __align__(16) __half g_a[NMAX * C];
// weights [conv][k][d][c] fp16, PRE-SWIZZLED for linear smem copy
__device__ __align__(16) __half g_wt[2 * KSZ * C * C];

// ---------------- helpers ----------------
static __device__ __forceinline__ uint32_t smem_u32(const void* p) {
    uint32_t a;
    asm("{ .reg .u64 t; cvta.to.shared.u64 t, %1; cvt.u32.u64 %0, t; }" : "=r"(a) : "l"(p));
    return a;
}
static __device__ __forceinline__ void cp_async16(uint32_t dst, const void* src) {
    asm volatile("cp.async.cg.shared.global [%0], [%1], 16;"
                 :: "r"(dst), "l"(__cvta_generic_to_global(src)) : "memory");
}
static __device__ __forceinline__ void cp_commit() {
    asm volatile("cp.async.commit_group;" ::: "memory");
}
static __device__ __forceinline__ void cp_wait1() {
    asm volatile("cp.async.wait_group 1;" ::: "memory");
}
static __device__ __forceinline__ void ldm4(uint32_t* r, uint32_t addr) {
    asm volatile("ldmatrix.sync.aligned.m8n8.x4.shared.b16 {%0,%1,%2,%3}, [%4];"
                 : "=r"(r[0]), "=r"(r[1]), "=r"(r[2]), "=r"(r[3]) : "r"(addr));
}
static __device__ __forceinline__ void mma_f16(float* c, const uint32_t* a, const uint32_t* b) {
    asm volatile(
        "mma.sync.aligned.m16n8k16.row.col.f32.f16.f16.f32 "
        "{%0,%1,%2,%3}, {%4,%5,%6,%7}, {%8,%9}, {%0,%1,%2,%3};"
        : "+f"(c[0]), "+f"(c[1]), "+f"(c[2]), "+f"(c[3])
        : "r"(a[0]), "r"(a[1]), "r"(a[2]), "r"(a[3]), "r"(b[0]), "r"(b[1]));
}

// ---------------- small kernels ----------------
__global__ void zero_stats_kernel() {
    int t = threadIdx.x;
    if (t < C) { g_sum1[t] = 0.f; g_sq1[t] = 0.f; g_sum2[t] = 0.f; g_sq2[t] = 0.f; }
}

// weights: logical [k][c][d] -> [conv][k][d][c] fp16, pre-swizzled
// row = d (128B = 8 segs of 16B = 8 halves each); seg s stored at (s ^ (d&7))
__global__ void prep_w_kernel(const float* __restrict__ W1, const float* __restrict__ W2) {
    int b = blockIdx.x;             // 0..2*KSZ-1
    int conv = b / KSZ, k = b % KSZ;
    const float* W = (conv == 0) ? W1 : W2;
    for (int i = threadIdx.x; i < C * C; i += blockDim.x) {
        int c = i >> 6, d = i & 63;
        float v = W[k * C * C + c * C + d];
        uint32_t sseg = (uint32_t)((c >> 3) ^ (d & 7));
        uint32_t idx = (uint32_t)(conv * KSZ + k) * 4096u
                     + (uint32_t)d * 64u + sseg * 8u + (uint32_t)(c & 7);
        g_wt[idx] = __float2half_rn(v);
    }
}

// feats -> fp16
__global__ void prep_feats_kernel(const float* __restrict__ feats, int n) {
    int i = blockIdx.x * blockDim.x + threadIdx.x;     // float4 index
    int total = n * (C / 4);
    if (i >= total) return;
    float4 v = ((const float4*)feats)[i];
    __half2 a = __floats2half2_rn(v.x, v.y);
    __half2 b = __floats2half2_rn(v.z, v.w);
    ((uint2*)g_a)[i] = make_uint2(*(uint32_t*)&a, *(uint32_t*)&b);
}

// y1 -> BN1+ReLU -> fp16 (overwrites g_a)
__global__ void prep_h1_kernel(int n) {
    int i = blockIdx.x * blockDim.x + threadIdx.x;
    int total = n * (C / 4);
    if (i >= total) return;
    int c = (i & 15) * 4;
    float4 v = ((const float4*)g_y1)[i];
    v.x = fmaxf(fmaf(v.x, g_scale1[c + 0], g_shift1[c + 0]), 0.f);
    v.y = fmaxf(fmaf(v.y, g_scale1[c + 1], g_shift1[c + 1]), 0.f);
    v.z = fmaxf(fmaf(v.z, g_scale1[c + 2], g_shift1[c + 2]), 0.f);
    v.w = fmaxf(fmaf(v.w, g_scale1[c + 3], g_shift1[c + 3]), 0.f);
    __half2 a = __floats2half2_rn(v.x, v.y);
    __half2 b = __floats2half2_rn(v.z, v.w);
    ((uint2*)g_a)[i] = make_uint2(*(uint32_t*)&a, *(uint32_t*)&b);
}

// ---------------- main conv (3-stage cp.async + ldmatrix + fp16 MMA) ----------------
template<int PASS>
__global__ __launch_bounds__(256, 2) void conv_mma_kernel(
    const int* __restrict__ nbr, const float* __restrict__ bias,
    float* __restrict__ dout, int n)
{
    extern __shared__ char dsm[];
    __shared__ float s_sum[C], s_sq[C], s_bias[C];

    float*       yout = (PASS == 0) ? g_y1   : dout;
    float*       gsum = (PASS == 0) ? g_sum1 : g_sum2;
    float*       gsq  = (PASS == 0) ? g_sq1  : g_sq2;

    const int tid = threadIdx.x, lane = tid & 31, w = tid >> 5;
    const uint32_t base = (smem_u32(dsm) + 1023u) & ~1023u;

    if (tid < C) { s_sum[tid] = 0.f; s_sq[tid] = 0.f; s_bias[tid] = bias[tid]; }

    // ---- copy-role mapping: 8 segs (16B) per 128B row ----
    const int cseg = tid & 7;
    const int crow = tid >> 3;                 // 0..31, rows crow + 32i
    const long blk0 = (long)blockIdx.x * TM;

    const uint4* gw = (const uint4*)g_wt + (size_t)PASS * KSZ * 512;

    int pidx[4];
    auto load_idx = [&](int k) {
        #pragma unroll
        for (int i = 0; i < 4; ++i) {
            long r = blk0 + crow + 32 * i;
            pidx[i] = (r < (long)n) ? nbr[r * KSZ + k] : 0;
        }
    };
    auto issue_stage = [&](int k) {
        const int s = k % 3;
        const uint32_t Ast = base + (uint32_t)s * STAGE_BYTES;
        const uint32_t Wst = Ast + 16384u;
        #pragma unroll
        for (int i = 0; i < 4; ++i) {
            int r = crow + 32 * i;
            uint32_t dst = (uint32_t)r * 128u + (uint32_t)((cseg ^ (r & 7)) << 4);
            cp_async16(Ast + dst, g_a + (size_t)pidx[i] * 64 + cseg * 8);
        }
        #pragma unroll
        for (int i = 0; i < 2; ++i) {
            int j = tid + i * 256;
            cp_async16(Wst + (uint32_t)j * 16u, gw + (size_t)k * 512 + j);
        }
        cp_commit();
    };

    // ---- mma-role addressing (validated bf16/b16 layout) ----
    const int ar = w * 16 + (lane & 15);
    const int ahalf = lane >> 4;
    const uint32_t a_row_off = (uint32_t)ar * 128u;
    const int ax7 = ar & 7;
    const int bd = ((lane >> 4) & 1) * 8 + (lane & 7);
    const int bkh = (lane >> 3) & 1;
    const int bx7 = bd & 7;

    float acc[8][4];
    #pragma unroll
    for (int nt = 0; nt < 8; ++nt)
        #pragma unroll
        for (int j = 0; j < 4; ++j) acc[nt][j] = 0.f;

    // ---- prologue: fill 2 stages ----
    load_idx(0);
    issue_stage(0);
    load_idx(1);
    issue_stage(1);
    load_idx(2);

    for (int k = 0; k < KSZ; ++k) {
        cp_wait1();
        __syncthreads();          // stage k ready; buffer (k+2)%3 free

        if (k + 2 < KSZ) {
            issue_stage(k + 2);
            if (k + 3 < KSZ) load_idx(k + 3);
        }

        const int s = k % 3;
        const uint32_t Ast = base + (uint32_t)s * STAGE_BYTES;
        const uint32_t Wst = Ast + 16384u;

        #pragma unroll
        for (int kk = 0; kk < 4; ++kk) {
            uint32_t a[4];
            uint32_t aoff = a_row_off + (uint32_t)(((kk * 2 + ahalf) ^ ax7) << 4);
            ldm4(a, Ast + aoff);
            uint32_t bseg = (uint32_t)(((kk * 2 + bkh) ^ bx7) << 4);
            #pragma unroll
            for (int p = 0; p < 4; ++p) {
                uint32_t b[4];
                uint32_t boff = (uint32_t)(p * 16 + bd) * 128u + bseg;
                ldm4(b, Wst + boff);
                mma_f16(acc[2 * p],     a, b);
                mma_f16(acc[2 * p + 1], a, b + 2);
            }
        }
    }

    // ---------------- epilogue ----------------
    const int g = lane >> 2, tig = lane & 3;
    const long row0 = blk0 + w * 16 + g;
    const long row1 = row0 + 8;
    const bool v0 = row0 < (long)n, v1 = row1 < (long)n;

    #pragma unroll
    for (int nt = 0; nt < 8; ++nt) {
        int col = nt * 8 + tig * 2;
        float b0 = s_bias[col], b1 = s_bias[col + 1];
        float y00 = v0 ? acc[nt][0] + b0 : 0.f;
        float y01 = v0 ? acc[nt][1] + b1 : 0.f;
        float y10 = v1 ? acc[nt][2] + b0 : 0.f;
        float y11 = v1 ? acc[nt][3] + b1 : 0.f;
        if (v0) *(float2*)(yout + (size_t)row0 * C + col) = make_float2(y00, y01);
        if (v1) *(float2*)(yout + (size_t)row1 * C + col) = make_float2(y10, y11);
        float sv0 = y00 + y10, sv1 = y01 + y11;
        float sq0 = y00 * y00 + y10 * y10, sq1 = y01 * y01 + y11 * y11;
        #pragma unroll
        for (int o = 16; o >= 4; o >>= 1) {
            sv0 += __shfl_xor_sync(0xffffffffu, sv0, o);
            sv1 += __shfl_xor_sync(0xffffffffu, sv1, o);
            sq0 += __shfl_xor_sync(0xffffffffu, sq0, o);
            sq1 += __shfl_xor_sync(0xffffffffu, sq1, o);
        }
        if (lane < 4) {
            atomicAdd(&s_sum[col], sv0); atomicAdd(&s_sum[col + 1], sv1);
            atomicAdd(&s_sq[col],  sq0); atomicAdd(&s_sq[col + 1],  sq1);
        }
    }
    __syncthreads();
    if (tid < C) { atomicAdd(&gsum[tid], s_sum[tid]); atomicAdd(&gsq[tid], s_sq[tid]); }
}

template<int PASS>
__global__ void stats_kernel(const float* __restrict__ gamma,
                             const float* __restrict__ beta, int n) {
    int d = threadIdx.x;
    if (d >= C) return;
    float sum = (PASS == 0) ? g_sum1[d] : g_sum2[d];
    float sq  = (PASS == 0) ? g_sq1[d]  : g_sq2[d];
    float inv_n = 1.0f / (float)n;
    float mean = sum * inv_n;
    float var = fmaxf(sq * inv_n - mean * mean, 0.f);
    float sc = gamma[d] * rsqrtf(var + EPSV);
    float sh = beta[d] - mean * sc;
    if (PASS == 0) { g_scale1[d] = sc; g_shift1[d] = sh; }
    else           { g_scale2[d] = sc; g_shift2[d] = sh; }
}

__global__ void final_kernel(const float* __restrict__ feats,
                             float* __restrict__ out, int n) {
    int i = blockIdx.x * blockDim.x + threadIdx.x;
    int total = n * (C / 4);
    if (i >= total) return;
    int c = (i & 15) * 4;
    float4 y = ((const float4*)out)[i];
    float4 f = ((const float4*)feats)[i];
    float4 r;
    r.x = fmaxf(fmaf(y.x, g_scale2[c + 0], g_shift2[c + 0]) + f.x, 0.f);
    r.y = fmaxf(fmaf(y.y, g_scale2[c + 1], g_shift2[c + 1]) + f.y, 0.f);
    r.z = fmaxf(fmaf(y.z, g_scale2[c + 2], g_shift2[c + 2]) + f.z, 0.f);
    r.w = fmaxf(fmaf(y.w, g_scale2[c + 3], g_shift2[c + 3]) + f.w, 0.f);
    ((float4*)out)[i] = r;
}

extern "C" void kernel_launch(void* const* d_in, const int* in_sizes, int n_in,
                              void* d_out, int out_size) {
    const float* feats = (const float*)d_in[0];
    const int*   nbr   = (const int*)d_in[1];
    const float* W1    = (const float*)d_in[2];
    const float* b1    = (const float*)d_in[3];
    const float* g1    = (const float*)d_in[4];
    const float* be1   = (const float*)d_in[5];
    const float* W2    = (const float*)d_in[6];
    const float* b2    = (const float*)d_in[7];
    const float* g2    = (const float*)d_in[8];
    const float* be2   = (const float*)d_in[9];
    float* out = (float*)d_out;

    int n = in_sizes[0] / C;
    int conv_blocks = (n + TM - 1) / TM;
    int ew_blocks = (n * (C / 4) + 255) / 256;

    cudaFuncSetAttribute(conv_mma_kernel<0>, cudaFuncAttributeMaxDynamicSharedMemorySize, SMEM_DYN);
    cudaFuncSetAttribute(conv_mma_kernel<1>, cudaFuncAttributeMaxDynamicSharedMemorySize, SMEM_DYN);

    zero_stats_kernel<<<1, 64>>>();
    prep_w_kernel<<<2 * KSZ, 256>>>(W1, W2);
    prep_feats_kernel<<<ew_blocks, 256>>>(feats, n);
    conv_mma_kernel<0><<<conv_blocks, 256, SMEM_DYN>>>(nbr, b1, nullptr, n);
    stats_kernel<0><<<1, 64>>>(g1, be1, n);
    prep_h1_kernel<<<ew_blocks, 256>>>(n);
    conv_mma_kernel<1><<<conv_blocks, 256, SMEM_DYN>>>(nbr, b2, out, n);
    stats_kernel<1><<<1, 64>>>(g2, be2, n);
    final_kernel<<<ew_blocks, 256>>>(feats, out, n);
}

// round 9
// speedup vs baseline: 5.5532x; 1.0557x over previous
#include <cuda_runtime.h>
#include <cuda_fp16.h>
#include <cstdint>

#define C 64
#define KSZ 27
#define KPAD 28
#define NPAIR 14
#define TM 128
#define NMAX 100000
#define EPSV 1e-5f

// stage = A(2 offsets, 16KB each) + W(2 offsets, 8KB each) = 48KB; 2 stages
#define STAGE_BYTES 49152
#define SMEM_DYN (2 * STAGE_BYTES + 1024)

// Device scratch (no allocation allowed)
__device__ float g_y1[NMAX * C];
__device__ float g_sum1[C], g_sq1[C], g_sum2[C], g_sq2[C];
// fp16 activations, row-major [n][64] (128B rows)
__device__ __align__(16) __half g_a[NMAX * C];
// weights [conv][kpad=28][d][c] fp16, PRE-SWIZZLED; tile 27 is zero pad
__device__ __align__(16) __half g_wt[2 * KPAD * C * C];

// ---------------- helpers ----------------
static __device__ __forceinline__ uint32_t smem_u32(const void* p) {
    uint32_t a;
    asm("{ .reg .u64 t; cvta.to.shared.u64 t, %1; cvt.u32.u64 %0, t; }" : "=r"(a) : "l"(p));
    return a;
}
static __device__ __forceinline__ void cp_async16(uint32_t dst, const void* src) {
    asm volatile("cp.async.cg.shared.global [%0], [%1], 16;"
                 :: "r"(dst), "l"(__cvta_generic_to_global(src)) : "memory");
}
static __device__ __forceinline__ void cp_commit() {
    asm volatile("cp.async.commit_group;" ::: "memory");
}
static __device__ __forceinline__ void cp_wait0() {
    asm volatile("cp.async.wait_group 0;" ::: "memory");
}
static __device__ __forceinline__ void ldm4(uint32_t* r, uint32_t addr) {
    asm volatile("ldmatrix.sync.aligned.m8n8.x4.shared.b16 {%0,%1,%2,%3}, [%4];"
                 : "=r"(r[0]), "=r"(r[1]), "=r"(r[2]), "=r"(r[3]) : "r"(addr));
}
static __device__ __forceinline__ void mma_f16(float* c, const uint32_t* a, const uint32_t* b) {
    asm volatile(
        "mma.sync.aligned.m16n8k16.row.col.f32.f16.f16.f32 "
        "{%0,%1,%2,%3}, {%4,%5,%6,%7}, {%8,%9}, {%0,%1,%2,%3};"
        : "+f"(c[0]), "+f"(c[1]), "+f"(c[2]), "+f"(c[3])
        : "r"(a[0]), "r"(a[1]), "r"(a[2]), "r"(a[3]), "r"(b[0]), "r"(b[1]));
}

// ---------------- fused prep: zero stats + W prep (+pad) + feats->fp16 ----------------
__global__ void prep_all_kernel(const float* __restrict__ W1, const float* __restrict__ W2,
                                const float* __restrict__ feats, int n) {
    int b = blockIdx.x, tid = threadIdx.x;
    if (b == 0 && tid < C) {
        g_sum1[tid] = 0.f; g_sq1[tid] = 0.f; g_sum2[tid] = 0.f; g_sq2[tid] = 0.f;
    }
    if (b < 2 * KPAD) {
        int conv = b / KPAD, k = b % KPAD;
        __half* dst = g_wt + (size_t)b * C * C;
        if (k == KSZ) {               // zero pad tile
            uint4 z = make_uint4(0, 0, 0, 0);
            ((uint4*)dst)[tid] = z;
            ((uint4*)dst)[tid + 256] = z;
            return;
        }
        const float* W = ((conv == 0) ? W1 : W2) + (size_t)k * C * C;
        #pragma unroll
        for (int i = 0; i < 16; ++i) {
            int e = tid + i * 256;     // 0..4095
            int c = e >> 6, d = e & 63;
            float v = W[c * C + d];
            uint32_t sseg = (uint32_t)((c >> 3) ^ (d & 7));
            dst[(uint32_t)d * 64u + sseg * 8u + (uint32_t)(c & 7)] = __float2half_rn(v);
        }
        return;
    }
    int i = (b - 2 * KPAD) * 256 + tid;        // float4 index
    int total = n * (C / 4);
    if (i >= total) return;
    float4 v = ((const float4*)feats)[i];
    __half2 a = __floats2half2_rn(v.x, v.y);
    __half2 bb = __floats2half2_rn(v.z, v.w);
    ((uint2*)g_a)[i] = make_uint2(*(uint32_t*)&a, *(uint32_t*)&bb);
}

// y1 -> BN1(inline stats)+ReLU -> fp16 (overwrites g_a)
__global__ void prep_h1_kernel(const float* __restrict__ gamma,
                               const float* __restrict__ beta, int n) {
    __shared__ float s_sc[C], s_sh[C];
    int tid = threadIdx.x;
    if (tid < C) {
        float inv_n = 1.0f / (float)n;
        float mean = g_sum1[tid] * inv_n;
        float var = fmaxf(g_sq1[tid] * inv_n - mean * mean, 0.f);
        float sc = gamma[tid] * rsqrtf(var + EPSV);
        s_sc[tid] = sc;
        s_sh[tid] = beta[tid] - mean * sc;
    }
    __syncthreads();
    int i = blockIdx.x * blockDim.x + tid;
    int total = n * (C / 4);
    if (i >= total) return;
    int c = (i & 15) * 4;
    float4 v = ((const float4*)g_y1)[i];
    v.x = fmaxf(fmaf(v.x, s_sc[c + 0], s_sh[c + 0]), 0.f);
    v.y = fmaxf(fmaf(v.y, s_sc[c + 1], s_sh[c + 1]), 0.f);
    v.z = fmaxf(fmaf(v.z, s_sc[c + 2], s_sh[c + 2]), 0.f);
    v.w = fmaxf(fmaf(v.w, s_sc[c + 3], s_sh[c + 3]), 0.f);
    __half2 a = __floats2half2_rn(v.x, v.y);
    __half2 b = __floats2half2_rn(v.z, v.w);
    ((uint2*)g_a)[i] = make_uint2(*(uint32_t*)&a, *(uint32_t*)&b);
}

// out = relu(bn2(y2)+feats), stats2 inlined
__global__ void final_kernel(const float* __restrict__ feats,
                             const float* __restrict__ gamma,
                             const float* __restrict__ beta,
                             float* __restrict__ out, int n) {
    __shared__ float s_sc[C], s_sh[C];
    int tid = threadIdx.x;
    if (tid < C) {
        float inv_n = 1.0f / (float)n;
        float mean = g_sum2[tid] * inv_n;
        float var = fmaxf(g_sq2[tid] * inv_n - mean * mean, 0.f);
        float sc = gamma[tid] * rsqrtf(var + EPSV);
        s_sc[tid] = sc;
        s_sh[tid] = beta[tid] - mean * sc;
    }
    __syncthreads();
    int i = blockIdx.x * blockDim.x + tid;
    int total = n * (C / 4);
    if (i >= total) return;
    int c = (i & 15) * 4;
    float4 y = ((const float4*)out)[i];
    float4 f = ((const float4*)feats)[i];
    float4 r;
    r.x = fmaxf(fmaf(y.x, s_sc[c + 0], s_sh[c + 0]) + f.x, 0.f);
    r.y = fmaxf(fmaf(y.y, s_sc[c + 1], s_sh[c + 1]) + f.y, 0.f);
    r.z = fmaxf(fmaf(y.z, s_sc[c + 2], s_sh[c + 2]) + f.z, 0.f);
    r.w = fmaxf(fmaf(y.w, s_sc[c + 3], s_sh[c + 3]) + f.w, 0.f);
    ((float4*)out)[i] = r;
}

// ---------------- main conv: 2 offsets/stage, 2-stage cp.async pipeline ----------------
template<int PASS>
__global__ __launch_bounds__(256, 2) void conv_mma_kernel(
    const int* __restrict__ nbr, const float* __restrict__ bias,
    float* __restrict__ dout, int n)
{
    extern __shared__ char dsm[];
    __shared__ float s_sum[C], s_sq[C], s_bias[C];

    float*       yout = (PASS == 0) ? g_y1   : dout;
    float*       gsum = (PASS == 0) ? g_sum1 : g_sum2;
    float*       gsq  = (PASS == 0) ? g_sq1  : g_sq2;

    const int tid = threadIdx.x, lane = tid & 31, w = tid >> 5;
    const uint32_t base = (smem_u32(dsm) + 1023u) & ~1023u;

    if (tid < C) { s_sum[tid] = 0.f; s_sq[tid] = 0.f; s_bias[tid] = bias[tid]; }

    // ---- copy-role: 8 segs (16B) per 128B row; 4 rows per thread per offset ----
    const int cseg = tid & 7;
    const int crow = tid >> 3;                 // 0..31
    const long blk0 = (long)blockIdx.x * TM;

    const uint4* gw = (const uint4*)g_wt + (size_t)PASS * KPAD * 512;

    int pidx[2][4];
    auto load_idx = [&](int j) {               // pair j -> offsets 2j, 2j+1
        #pragma unroll
        for (int o = 0; o < 2; ++o) {
            int k = 2 * j + o;
            #pragma unroll
            for (int i = 0; i < 4; ++i) {
                long r = blk0 + crow + 32 * i;
                pidx[o][i] = (r < (long)n && k < KSZ) ? nbr[r * KSZ + k] : 0;
            }
        }
    };
    auto issue_stage = [&](int j) {
        const uint32_t St = base + (uint32_t)(j & 1) * STAGE_BYTES;
        #pragma unroll
        for (int o = 0; o < 2; ++o) {
            const uint32_t Ao = St + (uint32_t)o * 16384u;
            const uint32_t Wo = St + 32768u + (uint32_t)o * 8192u;
            #pragma unroll
            for (int i = 0; i < 4; ++i) {
                int r = crow + 32 * i;
                uint32_t dst = (uint32_t)r * 128u + (uint32_t)((cseg ^ (r & 7)) << 4);
                cp_async16(Ao + dst, g_a + (size_t)pidx[o][i] * 64 + cseg * 8);
            }
            int k = 2 * j + o;
            #pragma unroll
            for (int i = 0; i < 2; ++i) {
                int jj = tid + i * 256;
                cp_async16(Wo + (uint32_t)jj * 16u, gw + (size_t)k * 512 + jj);
            }
        }
        cp_commit();
    };

    // ---- mma-role addressing ----
    const int ar = w * 16 + (lane & 15);
    const int ahalf = lane >> 4;
    const uint32_t a_row_off = (uint32_t)ar * 128u;
    const int ax7 = ar & 7;
    const int bd = ((lane >> 4) & 1) * 8 + (lane & 7);
    const int bkh = (lane >> 3) & 1;
    const int bx7 = bd & 7;

    float acc[8][4];
    #pragma unroll
    for (int nt = 0; nt < 8; ++nt)
        #pragma unroll
        for (int j = 0; j < 4; ++j) acc[nt][j] = 0.f;

    // ---- prologue ----
    load_idx(0);
    issue_stage(0);
    load_idx(1);

    for (int j = 0; j < NPAIR; ++j) {
        cp_wait0();
        __syncthreads();          // stage j ready; other stage free

        if (j + 1 < NPAIR) {
            issue_stage(j + 1);
            if (j + 2 < NPAIR) load_idx(j + 2);
        }

        const uint32_t St = base + (uint32_t)(j & 1) * STAGE_BYTES;
        #pragma unroll
        for (int o = 0; o < 2; ++o) {
            const uint32_t Ao = St + (uint32_t)o * 16384u;
            const uint32_t Wo = St + 32768u + (uint32_t)o * 8192u;
            #pragma unroll
            for (int kk = 0; kk < 4; ++kk) {
                uint32_t a[4];
                ldm4(a, Ao + a_row_off + (uint32_t)(((kk * 2 + ahalf) ^ ax7) << 4));
                uint32_t bseg = (uint32_t)(((kk * 2 + bkh) ^ bx7) << 4);
                #pragma unroll
                for (int p = 0; p < 4; ++p) {
                    uint32_t b[4];
                    ldm4(b, Wo + (uint32_t)(p * 16 + bd) * 128u + bseg);
                    mma_f16(acc[2 * p],     a, b);
                    mma_f16(acc[2 * p + 1], a, b + 2);
                }
            }
        }
    }

    // ---------------- epilogue ----------------
    const int g = lane >> 2, tig = lane & 3;
    const long row0 = blk0 + w * 16 + g;
    const long row1 = row0 + 8;
    const bool v0 = row0 < (long)n, v1 = row1 < (long)n;

    #pragma unroll
    for (int nt = 0; nt < 8; ++nt) {
        int col = nt * 8 + tig * 2;
        float b0 = s_bias[col], b1 = s_bias[col + 1];
        float y00 = v0 ? acc[nt][0] + b0 : 0.f;
        float y01 = v0 ? acc[nt][1] + b1 : 0.f;
        float y10 = v1 ? acc[nt][2] + b0 : 0.f;
        float y11 = v1 ? acc[nt][3] + b1 : 0.f;
        if (v0) *(float2*)(yout + (size_t)row0 * C + col) = make_float2(y00, y01);
        if (v1) *(float2*)(yout + (size_t)row1 * C + col) = make_float2(y10, y11);
        float sv0 = y00 + y10, sv1 = y01 + y11;
        float sq0 = y00 * y00 + y10 * y10, sq1 = y01 * y01 + y11 * y11;
        #pragma unroll
        for (int o = 16; o >= 4; o >>= 1) {
            sv0 += __shfl_xor_sync(0xffffffffu, sv0, o);
            sv1 += __shfl_xor_sync(0xffffffffu, sv1, o);
            sq0 += __shfl_xor_sync(0xffffffffu, sq0, o);
            sq1 += __shfl_xor_sync(0xffffffffu, sq1, o);
        }
        if (lane < 4) {
            atomicAdd(&s_sum[col], sv0); atomicAdd(&s_sum[col + 1], sv1);
            atomicAdd(&s_sq[col],  sq0); atomicAdd(&s_sq[col + 1],  sq1);
        }
    }
    __syncthreads();
    if (tid < C) { atomicAdd(&gsum[tid], s_sum[tid]); atomicAdd(&gsq[tid], s_sq[tid]); }
}

extern "C" void kernel_launch(void* const* d_in, const int* in_sizes, int n_in,
                              void* d_out, int out_size) {
    const float* feats = (const float*)d_in[0];
    const int*   nbr   = (const int*)d_in[1];
    const float* W1    = (const float*)d_in[2];
    const float* b1    = (const float*)d_in[3];
    const float* g1    = (const float*)d_in[4];
    const float* be1   = (const float*)d_in[5];
    const float* W2    = (const float*)d_in[6];
    const float* b2    = (const float*)d_in[7];
    const float* g2    = (const float*)d_in[8];
    const float* be2   = (const float*)d_in[9];
    float* out = (float*)d_out;

    int n = in_sizes[0] / C;
    int conv_blocks = (n + TM - 1) / TM;
    int ew_blocks = (n * (C / 4) + 255) / 256;

    cudaFuncSetAttribute(conv_mma_kernel<0>, cudaFuncAttributeMaxDynamicSharedMemorySize, SMEM_DYN);
    cudaFuncSetAttribute(conv_mma_kernel<1>, cudaFuncAttributeMaxDynamicSharedMemorySize, SMEM_DYN);

    prep_all_kernel<<<2 * KPAD + ew_blocks, 256>>>(W1, W2, feats, n);
    conv_mma_kernel<0><<<conv_blocks, 256, SMEM_DYN>>>(nbr, b1, nullptr, n);
    prep_h1_kernel<<<ew_blocks, 256>>>(g1, be1, n);
    conv_mma_kernel<1><<<conv_blocks, 256, SMEM_DYN>>>(nbr, b2, out, n);
    final_kernel<<<ew_blocks, 256>>>(feats, g2, be2, out, n);
}

// round 10
// speedup vs baseline: 6.4062x; 1.1536x over previous
#include <cuda_runtime.h>
#include <cuda_fp16.h>
#include <cstdint>

#define C 64
#define KSZ 27
#define TM 128
#define NMAX 100000
#define EPSV 1e-5f

// 4 stages, each: A 16KB + W 8KB = 24KB
#define STAGE_BYTES 24576
#define SMEM_DYN (4 * STAGE_BYTES + 1024)

// Device scratch (no allocation allowed)
__device__ float g_y1[NMAX * C];
__device__ float g_sum1[C], g_sq1[C], g_sum2[C], g_sq2[C];
// fp16 activations, row-major [n][64] (128B rows)
__device__ __align__(16) __half g_a[NMAX * C];
// weights [conv][k][d][c] fp16, PRE-SWIZZLED for linear smem copy
__device__ __align__(16) __half g_wt[2 * KSZ * C * C];

// ---------------- helpers ----------------
static __device__ __forceinline__ uint32_t smem_u32(const void* p) {
    uint32_t a;
    asm("{ .reg .u64 t; cvta.to.shared.u64 t, %1; cvt.u32.u64 %0, t; }" : "=r"(a) : "l"(p));
    return a;
}
static __device__ __forceinline__ void cp_async16(uint32_t dst, const void* src) {
    asm volatile("cp.async.cg.shared.global [%0], [%1], 16;"
                 :: "r"(dst), "l"(__cvta_generic_to_global(src)) : "memory");
}
static __device__ __forceinline__ void cp_commit() {
    asm volatile("cp.async.commit_group;" ::: "memory");
}
static __device__ __forceinline__ void cp_wait2() {
    asm volatile("cp.async.wait_group 2;" ::: "memory");
}
static __device__ __forceinline__ void ldm4(uint32_t* r, uint32_t addr) {
    asm volatile("ldmatrix.sync.aligned.m8n8.x4.shared.b16 {%0,%1,%2,%3}, [%4];"
                 : "=r"(r[0]), "=r"(r[1]), "=r"(r[2]), "=r"(r[3]) : "r"(addr));
}
static __device__ __forceinline__ void mma_f16(float* c, const uint32_t* a, const uint32_t* b) {
    asm volatile(
        "mma.sync.aligned.m16n8k16.row.col.f32.f16.f16.f32 "
        "{%0,%1,%2,%3}, {%4,%5,%6,%7}, {%8,%9}, {%0,%1,%2,%3};"
        : "+f"(c[0]), "+f"(c[1]), "+f"(c[2]), "+f"(c[3])
        : "r"(a[0]), "r"(a[1]), "r"(a[2]), "r"(a[3]), "r"(b[0]), "r"(b[1]));
}

// ---------------- fused prep: zero stats + W prep + feats->fp16 ----------------
__global__ void prep_all_kernel(const float* __restrict__ W1, const float* __restrict__ W2,
                                const float* __restrict__ feats, int n) {
    int b = blockIdx.x, tid = threadIdx.x;
    if (b == 0 && tid < C) {
        g_sum1[tid] = 0.f; g_sq1[tid] = 0.f; g_sum2[tid] = 0.f; g_sq2[tid] = 0.f;
    }
    if (b < 2 * KSZ) {
        int conv = b / KSZ, k = b % KSZ;
        __half* dst = g_wt + (size_t)b * C * C;
        const float* W = ((conv == 0) ? W1 : W2) + (size_t)k * C * C;
        #pragma unroll
        for (int i = 0; i < 16; ++i) {
            int e = tid + i * 256;     // 0..4095
            int c = e >> 6, d = e & 63;
            float v = W[c * C + d];
            uint32_t sseg = (uint32_t)((c >> 3) ^ (d & 7));
            dst[(uint32_t)d * 64u + sseg * 8u + (uint32_t)(c & 7)] = __float2half_rn(v);
        }
        return;
    }
    int i = (b - 2 * KSZ) * 256 + tid;        // float4 index
    int total = n * (C / 4);
    if (i >= total) return;
    float4 v = ((const float4*)feats)[i];
    __half2 a = __floats2half2_rn(v.x, v.y);
    __half2 bb = __floats2half2_rn(v.z, v.w);
    ((uint2*)g_a)[i] = make_uint2(*(uint32_t*)&a, *(uint32_t*)&bb);
}

// y1 -> BN1(inline stats)+ReLU -> fp16 (overwrites g_a)
__global__ void prep_h1_kernel(const float* __restrict__ gamma,
                               const float* __restrict__ beta, int n) {
    __shared__ float s_sc[C], s_sh[C];
    int tid = threadIdx.x;
    if (tid < C) {
        float inv_n = 1.0f / (float)n;
        float mean = g_sum1[tid] * inv_n;
        float var = fmaxf(g_sq1[tid] * inv_n - mean * mean, 0.f);
        float sc = gamma[tid] * rsqrtf(var + EPSV);
        s_sc[tid] = sc;
        s_sh[tid] = beta[tid] - mean * sc;
    }
    __syncthreads();
    int i = blockIdx.x * blockDim.x + tid;
    int total = n * (C / 4);
    if (i >= total) return;
    int c = (i & 15) * 4;
    float4 v = ((const float4*)g_y1)[i];
    v.x = fmaxf(fmaf(v.x, s_sc[c + 0], s_sh[c + 0]), 0.f);
    v.y = fmaxf(fmaf(v.y, s_sc[c + 1], s_sh[c + 1]), 0.f);
    v.z = fmaxf(fmaf(v.z, s_sc[c + 2], s_sh[c + 2]), 0.f);
    v.w = fmaxf(fmaf(v.w, s_sc[c + 3], s_sh[c + 3]), 0.f);
    __half2 a = __floats2half2_rn(v.x, v.y);
    __half2 b = __floats2half2_rn(v.z, v.w);
    ((uint2*)g_a)[i] = make_uint2(*(uint32_t*)&a, *(uint32_t*)&b);
}

// out = relu(bn2(y2)+feats), stats2 inlined
__global__ void final_kernel(const float* __restrict__ feats,
                             const float* __restrict__ gamma,
                             const float* __restrict__ beta,
                             float* __restrict__ out, int n) {
    __shared__ float s_sc[C], s_sh[C];
    int tid = threadIdx.x;
    if (tid < C) {
        float inv_n = 1.0f / (float)n;
        float mean = g_sum2[tid] * inv_n;
        float var = fmaxf(g_sq2[tid] * inv_n - mean * mean, 0.f);
        float sc = gamma[tid] * rsqrtf(var + EPSV);
        s_sc[tid] = sc;
        s_sh[tid] = beta[tid] - mean * sc;
    }
    __syncthreads();
    int i = blockIdx.x * blockDim.x + tid;
    int total = n * (C / 4);
    if (i >= total) return;
    int c = (i & 15) * 4;
    float4 y = ((const float4*)out)[i];
    float4 f = ((const float4*)feats)[i];
    float4 r;
    r.x = fmaxf(fmaf(y.x, s_sc[c + 0], s_sh[c + 0]) + f.x, 0.f);
    r.y = fmaxf(fmaf(y.y, s_sc[c + 1], s_sh[c + 1]) + f.y, 0.f);
    r.z = fmaxf(fmaf(y.z, s_sc[c + 2], s_sh[c + 2]) + f.z, 0.f);
    r.w = fmaxf(fmaf(y.w, s_sc[c + 3], s_sh[c + 3]) + f.w, 0.f);
    ((float4*)out)[i] = r;
}

// ---------------- main conv: R=2/Nc=32 warp tiles, 4-stage cp.async ring ----------------
template<int PASS>
__global__ __launch_bounds__(256, 2) void conv_mma_kernel(
    const int* __restrict__ nbr, const float* __restrict__ bias,
    float* __restrict__ dout, int n)
{
    extern __shared__ char dsm[];
    __shared__ float s_sum[C], s_sq[C], s_bias[C];

    float*       yout = (PASS == 0) ? g_y1   : dout;
    float*       gsum = (PASS == 0) ? g_sum1 : g_sum2;
    float*       gsq  = (PASS == 0) ? g_sq1  : g_sq2;

    const int tid = threadIdx.x, lane = tid & 31, w = tid >> 5;
    const uint32_t base = (smem_u32(dsm) + 1023u) & ~1023u;

    if (tid < C) { s_sum[tid] = 0.f; s_sq[tid] = 0.f; s_bias[tid] = bias[tid]; }

    // ---- copy-role: 8 segs (16B) per 128B row; 4 rows per thread ----
    const int cseg = tid & 7;
    const int crow = tid >> 3;                 // 0..31
    const long blk0 = (long)blockIdx.x * TM;

    const uint4* gw = (const uint4*)g_wt + (size_t)PASS * KSZ * 512;

    int pidx[4];
    auto load_idx = [&](int k) {
        #pragma unroll
        for (int i = 0; i < 4; ++i) {
            long r = blk0 + crow + 32 * i;
            pidx[i] = (r < (long)n) ? nbr[r * KSZ + k] : 0;
        }
    };
    auto issue_stage = [&](int k) {
        const uint32_t St = base + (uint32_t)(k & 3) * STAGE_BYTES;
        const uint32_t Wst = St + 16384u;
        #pragma unroll
        for (int i = 0; i < 4; ++i) {
            int r = crow + 32 * i;
            uint32_t dst = (uint32_t)r * 128u + (uint32_t)((cseg ^ (r & 7)) << 4);
            cp_async16(St + dst, g_a + (size_t)pidx[i] * 64 + cseg * 8);
        }
        #pragma unroll
        for (int i = 0; i < 2; ++i) {
            int jj = tid + i * 256;
            cp_async16(Wst + (uint32_t)jj * 16u, gw + (size_t)k * 512 + jj);
        }
        cp_commit();
    };

    // ---- mma-role: warp = (rowpair, nhalf); 2 row-tiles x 32 cols ----
    const int nhalf = w & 1, rowpair = w >> 1;
    const int ar0 = rowpair * 32 + (lane & 15);        // tt=0 row; tt=1 adds 16
    const int ahalf = lane >> 4;
    const int ax7 = lane & 7;                          // (ar&7) for both tiles
    const int bd = ((lane >> 4) & 1) * 8 + (lane & 7);
    const int bkh = (lane >> 3) & 1;
    const int bx7 = bd & 7;
    const uint32_t brow0 = (uint32_t)(nhalf * 32 + bd);

    float acc[2][4][4];
    #pragma unroll
    for (int tt = 0; tt < 2; ++tt)
        #pragma unroll
        for (int nt = 0; nt < 4; ++nt)
            #pragma unroll
            for (int j = 0; j < 4; ++j) acc[tt][nt][j] = 0.f;

    // ---- prologue: fill 3 stages ----
    load_idx(0); issue_stage(0);
    load_idx(1); issue_stage(1);
    load_idx(2); issue_stage(2);
    load_idx(3);

    for (int k = 0; k < KSZ; ++k) {
        cp_wait2();
        __syncthreads();          // stage k ready; ring slot (k+3)&3 free

        if (k + 3 < KSZ) {
            issue_stage(k + 3);
            if (k + 4 < KSZ) load_idx(k + 4);
        }

        const uint32_t St = base + (uint32_t)(k & 3) * STAGE_BYTES;
        const uint32_t Wst = St + 16384u;

        #pragma unroll
        for (int kk = 0; kk < 4; ++kk) {
            uint32_t a0[4], a1[4];
            uint32_t asel = (uint32_t)(((kk * 2 + ahalf) ^ ax7) << 4);
            ldm4(a0, St + (uint32_t)ar0 * 128u + asel);
            ldm4(a1, St + (uint32_t)(ar0 + 16) * 128u + asel);
            uint32_t bsel = (uint32_t)(((kk * 2 + bkh) ^ bx7) << 4);
            #pragma unroll
            for (int p = 0; p < 2; ++p) {
                uint32_t b[4];
                ldm4(b, Wst + (brow0 + (uint32_t)p * 16u) * 128u + bsel);
                mma_f16(acc[0][2 * p],     a0, b);
                mma_f16(acc[0][2 * p + 1], a0, b + 2);
                mma_f16(acc[1][2 * p],     a1, b);
                mma_f16(acc[1][2 * p + 1], a1, b + 2);
            }
        }
    }

    // ---------------- epilogue ----------------
    const int g = lane >> 2, tig = lane & 3;

    #pragma unroll
    for (int nt = 0; nt < 4; ++nt) {
        int col = nhalf * 32 + nt * 8 + tig * 2;
        float b0 = s_bias[col], b1 = s_bias[col + 1];
        float sv0 = 0.f, sv1 = 0.f, sq0 = 0.f, sq1 = 0.f;
        #pragma unroll
        for (int tt = 0; tt < 2; ++tt) {
            long row0 = blk0 + rowpair * 32 + tt * 16 + g;
            long row1 = row0 + 8;
            bool v0 = row0 < (long)n, v1 = row1 < (long)n;
            float y00 = v0 ? acc[tt][nt][0] + b0 : 0.f;
            float y01 = v0 ? acc[tt][nt][1] + b1 : 0.f;
            float y10 = v1 ? acc[tt][nt][2] + b0 : 0.f;
            float y11 = v1 ? acc[tt][nt][3] + b1 : 0.f;
            if (v0) *(float2*)(yout + (size_t)row0 * C + col) = make_float2(y00, y01);
            if (v1) *(float2*)(yout + (size_t)row1 * C + col) = make_float2(y10, y11);
            sv0 += y00 + y10; sv1 += y01 + y11;
            sq0 += y00 * y00 + y10 * y10; sq1 += y01 * y01 + y11 * y11;
        }
        #pragma unroll
        for (int o = 16; o >= 4; o >>= 1) {
            sv0 += __shfl_xor_sync(0xffffffffu, sv0, o);
            sv1 += __shfl_xor_sync(0xffffffffu, sv1, o);
            sq0 += __shfl_xor_sync(0xffffffffu, sq0, o);
            sq1 += __shfl_xor_sync(0xffffffffu, sq1, o);
        }
        if (lane < 4 && (lane & 3) == tig) { /* lanes 0..3 hold tig 0..3 */ }
        if (lane < 4) {
            atomicAdd(&s_sum[nhalf * 32 + nt * 8 + lane * 2],     sv0);
            atomicAdd(&s_sum[nhalf * 32 + nt * 8 + lane * 2 + 1], sv1);
            atomicAdd(&s_sq[nhalf * 32 + nt * 8 + lane * 2],      sq0);
            atomicAdd(&s_sq[nhalf * 32 + nt * 8 + lane * 2 + 1],  sq1);
        }
    }
    __syncthreads();
    if (tid < C) { atomicAdd(&gsum[tid], s_sum[tid]); atomicAdd(&gsq[tid], s_sq[tid]); }
}

extern "C" void kernel_launch(void* const* d_in, const int* in_sizes, int n_in,
                              void* d_out, int out_size) {
    const float* feats = (const float*)d_in[0];
    const int*   nbr   = (const int*)d_in[1];
    const float* W1    = (const float*)d_in[2];
    const float* b1    = (const float*)d_in[3];
    const float* g1    = (const float*)d_in[4];
    const float* be1   = (const float*)d_in[5];
    const float* W2    = (const float*)d_in[6];
    const float* b2    = (const float*)d_in[7];
    const float* g2    = (const float*)d_in[8];
    const float* be2   = (const float*)d_in[9];
    float* out = (float*)d_out;

    int n = in_sizes[0] / C;
    int conv_blocks = (n + TM - 1) / TM;
    int ew_blocks = (n * (C / 4) + 255) / 256;

    cudaFuncSetAttribute(conv_mma_kernel<0>, cudaFuncAttributeMaxDynamicSharedMemorySize, SMEM_DYN);
    cudaFuncSetAttribute(conv_mma_kernel<1>, cudaFuncAttributeMaxDynamicSharedMemorySize, SMEM_DYN);

    prep_all_kernel<<<2 * KSZ + ew_blocks, 256>>>(W1, W2, feats, n);
    conv_mma_kernel<0><<<conv_blocks, 256, SMEM_DYN>>>(nbr, b1, nullptr, n);
    prep_h1_kernel<<<ew_blocks, 256>>>(g1, be1, n);
    conv_mma_kernel<1><<<conv_blocks, 256, SMEM_DYN>>>(nbr, b2, out, n);
    final_kernel<<<ew_blocks, 256>>>(feats, g2, be2, out, n);
}

// round 11
// speedup vs baseline: 6.4392x; 1.0052x over previous
#include <cuda_runtime.h>
#include <cuda_fp16.h>
#include <cstdint>

#define C 64
#define KSZ 27
#define TM 128
#define NMAX 100000
#define EPSV 1e-5f

// 4 stages, each: A 16KB + W 8KB = 24KB
#define STAGE_BYTES 24576
#define SMEM_DYN (4 * STAGE_BYTES + 1024)

// Device scratch (no allocation allowed)
__device__ float g_y1[NMAX * C];
__device__ float g_sum1[C], g_sq1[C], g_sum2[C], g_sq2[C];
// fp16 activations, row-major [n][64] (128B rows)
__device__ __align__(16) __half g_a[NMAX * C];
// weights [conv][k][d][c] fp16, PRE-SWIZZLED for linear smem copy
__device__ __align__(16) __half g_wt[2 * KSZ * C * C];

// ---------------- helpers ----------------
static __device__ __forceinline__ uint32_t smem_u32(const void* p) {
    uint32_t a;
    asm("{ .reg .u64 t; cvta.to.shared.u64 t, %1; cvt.u32.u64 %0, t; }" : "=r"(a) : "l"(p));
    return a;
}
static __device__ __forceinline__ void cp_async16(uint32_t dst, const void* src) {
    asm volatile("cp.async.cg.shared.global [%0], [%1], 16;"
                 :: "r"(dst), "l"(__cvta_generic_to_global(src)) : "memory");
}
static __device__ __forceinline__ void cp_commit() {
    asm volatile("cp.async.commit_group;" ::: "memory");
}
static __device__ __forceinline__ void cp_wait2() {
    asm volatile("cp.async.wait_group 2;" ::: "memory");
}
static __device__ __forceinline__ void ldm4(uint32_t* r, uint32_t addr) {
    asm volatile("ldmatrix.sync.aligned.m8n8.x4.shared.b16 {%0,%1,%2,%3}, [%4];"
                 : "=r"(r[0]), "=r"(r[1]), "=r"(r[2]), "=r"(r[3]) : "r"(addr));
}
// NOTE: non-volatile — pure register op; lets ptxas interleave with later ldm4s
static __device__ __forceinline__ void mma_f16(float* c, const uint32_t* a, const uint32_t* b) {
    asm("mma.sync.aligned.m16n8k16.row.col.f32.f16.f16.f32 "
        "{%0,%1,%2,%3}, {%4,%5,%6,%7}, {%8,%9}, {%0,%1,%2,%3};"
        : "+f"(c[0]), "+f"(c[1]), "+f"(c[2]), "+f"(c[3])
        : "r"(a[0]), "r"(a[1]), "r"(a[2]), "r"(a[3]), "r"(b[0]), "r"(b[1]));
}

// ---------------- fused prep: zero stats + W prep + feats->fp16 ----------------
__global__ void prep_all_kernel(const float* __restrict__ W1, const float* __restrict__ W2,
                                const float* __restrict__ feats, int n) {
    int b = blockIdx.x, tid = threadIdx.x;
    if (b == 0 && tid < C) {
        g_sum1[tid] = 0.f; g_sq1[tid] = 0.f; g_sum2[tid] = 0.f; g_sq2[tid] = 0.f;
    }
    if (b < 2 * KSZ) {
        int conv = b / KSZ, k = b % KSZ;
        __half* dst = g_wt + (size_t)b * C * C;
        const float* W = ((conv == 0) ? W1 : W2) + (size_t)k * C * C;
        #pragma unroll
        for (int i = 0; i < 16; ++i) {
            int e = tid + i * 256;     // 0..4095
            int c = e >> 6, d = e & 63;
            float v = W[c * C + d];
            uint32_t sseg = (uint32_t)((c >> 3) ^ (d & 7));
            dst[(uint32_t)d * 64u + sseg * 8u + (uint32_t)(c & 7)] = __float2half_rn(v);
        }
        return;
    }
    int i = (b - 2 * KSZ) * 256 + tid;        // float4 index
    int total = n * (C / 4);
    if (i >= total) return;
    float4 v = ((const float4*)feats)[i];
    __half2 a = __floats2half2_rn(v.x, v.y);
    __half2 bb = __floats2half2_rn(v.z, v.w);
    ((uint2*)g_a)[i] = make_uint2(*(uint32_t*)&a, *(uint32_t*)&bb);
}

// y1 -> BN1(inline stats)+ReLU -> fp16 (overwrites g_a)
__global__ void prep_h1_kernel(const float* __restrict__ gamma,
                               const float* __restrict__ beta, int n) {
    __shared__ float s_sc[C], s_sh[C];
    int tid = threadIdx.x;
    if (tid < C) {
        float inv_n = 1.0f / (float)n;
        float mean = g_sum1[tid] * inv_n;
        float var = fmaxf(g_sq1[tid] * inv_n - mean * mean, 0.f);
        float sc = gamma[tid] * rsqrtf(var + EPSV);
        s_sc[tid] = sc;
        s_sh[tid] = beta[tid] - mean * sc;
    }
    __syncthreads();
    int i = blockIdx.x * blockDim.x + tid;
    int total = n * (C / 4);
    if (i >= total) return;
    int c = (i & 15) * 4;
    float4 v = ((const float4*)g_y1)[i];
    v.x = fmaxf(fmaf(v.x, s_sc[c + 0], s_sh[c + 0]), 0.f);
    v.y = fmaxf(fmaf(v.y, s_sc[c + 1], s_sh[c + 1]), 0.f);
    v.z = fmaxf(fmaf(v.z, s_sc[c + 2], s_sh[c + 2]), 0.f);
    v.w = fmaxf(fmaf(v.w, s_sc[c + 3], s_sh[c + 3]), 0.f);
    __half2 a = __floats2half2_rn(v.x, v.y);
    __half2 b = __floats2half2_rn(v.z, v.w);
    ((uint2*)g_a)[i] = make_uint2(*(uint32_t*)&a, *(uint32_t*)&b);
}

// out = relu(bn2(y2)+feats), stats2 inlined
__global__ void final_kernel(const float* __restrict__ feats,
                             const float* __restrict__ gamma,
                             const float* __restrict__ beta,
                             float* __restrict__ out, int n) {
    __shared__ float s_sc[C], s_sh[C];
    int tid = threadIdx.x;
    if (tid < C) {
        float inv_n = 1.0f / (float)n;
        float mean = g_sum2[tid] * inv_n;
        float var = fmaxf(g_sq2[tid] * inv_n - mean * mean, 0.f);
        float sc = gamma[tid] * rsqrtf(var + EPSV);
        s_sc[tid] = sc;
        s_sh[tid] = beta[tid] - mean * sc;
    }
    __syncthreads();
    int i = blockIdx.x * blockDim.x + tid;
    int total = n * (C / 4);
    if (i >= total) return;
    int c = (i & 15) * 4;
    float4 y = ((const float4*)out)[i];
    float4 f = ((const float4*)feats)[i];
    float4 r;
    r.x = fmaxf(fmaf(y.x, s_sc[c + 0], s_sh[c + 0]) + f.x, 0.f);
    r.y = fmaxf(fmaf(y.y, s_sc[c + 1], s_sh[c + 1]) + f.y, 0.f);
    r.z = fmaxf(fmaf(y.z, s_sc[c + 2], s_sh[c + 2]) + f.z, 0.f);
    r.w = fmaxf(fmaf(y.w, s_sc[c + 3], s_sh[c + 3]) + f.w, 0.f);
    ((float4*)out)[i] = r;
}

// ---------------- main conv: R=2/Nc=32 warp tiles, 4-stage ring, frag pipeline ----------------
template<int PASS>
__global__ __launch_bounds__(256, 2) void conv_mma_kernel(
    const int* __restrict__ nbr, const float* __restrict__ bias,
    float* __restrict__ dout, int n)
{
    extern __shared__ char dsm[];
    __shared__ float s_sum[C], s_sq[C], s_bias[C];

    float*       yout = (PASS == 0) ? g_y1   : dout;
    float*       gsum = (PASS == 0) ? g_sum1 : g_sum2;
    float*       gsq  = (PASS == 0) ? g_sq1  : g_sq2;

    const int tid = threadIdx.x, lane = tid & 31, w = tid >> 5;
    const uint32_t base = (smem_u32(dsm) + 1023u) & ~1023u;

    if (tid < C) { s_sum[tid] = 0.f; s_sq[tid] = 0.f; s_bias[tid] = bias[tid]; }

    // ---- copy-role: 8 segs (16B) per 128B row; 4 rows per thread ----
    const int cseg = tid & 7;
    const int crow = tid >> 3;                 // 0..31
    const long blk0 = (long)blockIdx.x * TM;

    const uint4* gw = (const uint4*)g_wt + (size_t)PASS * KSZ * 512;

    int pidx[4];
    auto load_idx = [&](int k) {
        #pragma unroll
        for (int i = 0; i < 4; ++i) {
            long r = blk0 + crow + 32 * i;
            pidx[i] = (r < (long)n) ? nbr[r * KSZ + k] : 0;
        }
    };
    auto issue_stage = [&](int k) {
        const uint32_t St = base + (uint32_t)(k & 3) * STAGE_BYTES;
        const uint32_t Wst = St + 16384u;
        #pragma unroll
        for (int i = 0; i < 4; ++i) {
            int r = crow + 32 * i;
            uint32_t dst = (uint32_t)r * 128u + (uint32_t)((cseg ^ (r & 7)) << 4);
            cp_async16(St + dst, g_a + (size_t)pidx[i] * 64 + cseg * 8);
        }
        #pragma unroll
        for (int i = 0; i < 2; ++i) {
            int jj = tid + i * 256;
            cp_async16(Wst + (uint32_t)jj * 16u, gw + (size_t)k * 512 + jj);
        }
        cp_commit();
    };

    // ---- mma-role: warp = (rowpair, nhalf); 2 row-tiles x 32 cols ----
    const int nhalf = w & 1, rowpair = w >> 1;
    const int ar0 = rowpair * 32 + (lane & 15);
    const int ahalf = lane >> 4;
    const int ax7 = lane & 7;
    const int bd = ((lane >> 4) & 1) * 8 + (lane & 7);
    const int bkh = (lane >> 3) & 1;
    const int bx7 = bd & 7;
    const uint32_t brow0 = (uint32_t)(nhalf * 32 + bd);

    float acc[2][4][4];
    #pragma unroll
    for (int tt = 0; tt < 2; ++tt)
        #pragma unroll
        for (int nt = 0; nt < 4; ++nt)
            #pragma unroll
            for (int j = 0; j < 4; ++j) acc[tt][nt][j] = 0.f;

    // ---- prologue: fill 3 stages ----
    load_idx(0); issue_stage(0);
    load_idx(1); issue_stage(1);
    load_idx(2); issue_stage(2);
    load_idx(3);

    for (int k = 0; k < KSZ; ++k) {
        cp_wait2();
        __syncthreads();          // stage k ready; ring slot (k+3)&3 free

        if (k + 3 < KSZ) {
            issue_stage(k + 3);
            if (k + 4 < KSZ) load_idx(k + 4);
        }

        const uint32_t St = base + (uint32_t)(k & 3) * STAGE_BYTES;
        const uint32_t Wst = St + 16384u;

        // fragment pipeline: A frags double-buffered one kk ahead;
        // B frags for a kk issued back-to-back before that kk's MMAs.
        uint32_t a0[2][4], a1[2][4];
        {
            uint32_t asel0 = (uint32_t)((ahalf ^ ax7) << 4);
            ldm4(a0[0], St + (uint32_t)ar0 * 128u + asel0);
            ldm4(a1[0], St + (uint32_t)(ar0 + 16) * 128u + asel0);
        }
        #pragma unroll
        for (int kk = 0; kk < 4; ++kk) {
            const int cur = kk & 1, nxt = cur ^ 1;
            uint32_t b0[4], b1[4];
            uint32_t bsel = (uint32_t)(((kk * 2 + bkh) ^ bx7) << 4);
            ldm4(b0, Wst + brow0 * 128u + bsel);
            ldm4(b1, Wst + (brow0 + 16u) * 128u + bsel);
            if (kk < 3) {
                uint32_t aseln = (uint32_t)((((kk + 1) * 2 + ahalf) ^ ax7) << 4);
                ldm4(a0[nxt], St + (uint32_t)ar0 * 128u + aseln);
                ldm4(a1[nxt], St + (uint32_t)(ar0 + 16) * 128u + aseln);
            }
            mma_f16(acc[0][0], a0[cur], b0);
            mma_f16(acc[0][1], a0[cur], b0 + 2);
            mma_f16(acc[1][0], a1[cur], b0);
            mma_f16(acc[1][1], a1[cur], b0 + 2);
            mma_f16(acc[0][2], a0[cur], b1);
            mma_f16(acc[0][3], a0[cur], b1 + 2);
            mma_f16(acc[1][2], a1[cur], b1);
            mma_f16(acc[1][3], a1[cur], b1 + 2);
        }
    }

    // ---------------- epilogue ----------------
    const int g = lane >> 2, tig = lane & 3;

    #pragma unroll
    for (int nt = 0; nt < 4; ++nt) {
        int col = nhalf * 32 + nt * 8 + tig * 2;
        float b0 = s_bias[col], b1 = s_bias[col + 1];
        float sv0 = 0.f, sv1 = 0.f, sq0 = 0.f, sq1 = 0.f;
        #pragma unroll
        for (int tt = 0; tt < 2; ++tt) {
            long row0 = blk0 + rowpair * 32 + tt * 16 + g;
            long row1 = row0 + 8;
            bool v0 = row0 < (long)n, v1 = row1 < (long)n;
            float y00 = v0 ? acc[tt][nt][0] + b0 : 0.f;
            float y01 = v0 ? acc[tt][nt][1] + b1 : 0.f;
            float y10 = v1 ? acc[tt][nt][2] + b0 : 0.f;
            float y11 = v1 ? acc[tt][nt][3] + b1 : 0.f;
            if (v0) *(float2*)(yout + (size_t)row0 * C + col) = make_float2(y00, y01);
            if (v1) *(float2*)(yout + (size_t)row1 * C + col) = make_float2(y10, y11);
            sv0 += y00 + y10; sv1 += y01 + y11;
            sq0 += y00 * y00 + y10 * y10; sq1 += y01 * y01 + y11 * y11;
        }
        #pragma unroll
        for (int o = 16; o >= 4; o >>= 1) {
            sv0 += __shfl_xor_sync(0xffffffffu, sv0, o);
            sv1 += __shfl_xor_sync(0xffffffffu, sv1, o);
            sq0 += __shfl_xor_sync(0xffffffffu, sq0, o);
            sq1 += __shfl_xor_sync(0xffffffffu, sq1, o);
        }
        if (lane < 4) {
            atomicAdd(&s_sum[nhalf * 32 + nt * 8 + lane * 2],     sv0);
            atomicAdd(&s_sum[nhalf * 32 + nt * 8 + lane * 2 + 1], sv1);
            atomicAdd(&s_sq[nhalf * 32 + nt * 8 + lane * 2],      sq0);
            atomicAdd(&s_sq[nhalf * 32 + nt * 8 + lane * 2 + 1],  sq1);
        }
    }
    __syncthreads();
    if (tid < C) { atomicAdd(&gsum[tid], s_sum[tid]); atomicAdd(&gsq[tid], s_sq[tid]); }
}

extern "C" void kernel_launch(void* const* d_in, const int* in_sizes, int n_in,
                              void* d_out, int out_size) {
    const float* feats = (const float*)d_in[0];
    const int*   nbr   = (const int*)d_in[1];
    const float* W1    = (const float*)d_in[2];
    const float* b1    = (const float*)d_in[3];
    const float* g1    = (const float*)d_in[4];
    const float* be1   = (const float*)d_in[5];
    const float* W2    = (const float*)d_in[6];
    const float* b2    = (const float*)d_in[7];
    const float* g2    = (const float*)d_in[8];
    const float* be2   = (const float*)d_in[9];
    float* out = (float*)d_out;

    int n = in_sizes[0] / C;
    int conv_blocks = (n + TM - 1) / TM;
    int ew_blocks = (n * (C / 4) + 255) / 256;

    cudaFuncSetAttribute(conv_mma_kernel<0>, cudaFuncAttributeMaxDynamicSharedMemorySize, SMEM_DYN);
    cudaFuncSetAttribute(conv_mma_kernel<1>, cudaFuncAttributeMaxDynamicSharedMemorySize, SMEM_DYN);

    prep_all_kernel<<<2 * KSZ + ew_blocks, 256>>>(W1, W2, feats, n);
    conv_mma_kernel<0><<<conv_blocks, 256, SMEM_DYN>>>(nbr, b1, nullptr, n);
    prep_h1_kernel<<<ew_blocks, 256>>>(g1, be1, n);
    conv_mma_kernel<1><<<conv_blocks, 256, SMEM_DYN>>>(nbr, b2, out, n);
    final_kernel<<<ew_blocks, 256>>>(feats, g2, be2, out, n);
}

// round 12
// speedup vs baseline: 6.7800x; 1.0529x over previous
#include <cuda_runtime.h>
#include <cuda_fp16.h>
#include <cstdint>

#define C 64
#define KSZ 27
#define TM 128
#define NMAX 100000
#define EPSV 1e-5f

// 3 stages, each: A 16KB + W 8KB = 24KB -> 72KB dyn; 3 CTAs/SM target
#define STAGE_BYTES 24576
#define SMEM_DYN (3 * STAGE_BYTES + 1024)

// Device scratch (no allocation allowed)
__device__ float g_y1[NMAX * C];
__device__ float g_sum1[C], g_sq1[C], g_sum2[C], g_sq2[C];
// fp16 activations, row-major [n][64] (128B rows)
__device__ __align__(16) __half g_a[NMAX * C];
// weights [conv][k][d][c] fp16, PRE-SWIZZLED for linear smem copy
__device__ __align__(16) __half g_wt[2 * KSZ * C * C];

// ---------------- helpers ----------------
static __device__ __forceinline__ uint32_t smem_u32(const void* p) {
    uint32_t a;
    asm("{ .reg .u64 t; cvta.to.shared.u64 t, %1; cvt.u32.u64 %0, t; }" : "=r"(a) : "l"(p));
    return a;
}
static __device__ __forceinline__ void cp_async16(uint32_t dst, const void* src) {
    asm volatile("cp.async.cg.shared.global [%0], [%1], 16;"
                 :: "r"(dst), "l"(__cvta_generic_to_global(src)) : "memory");
}
static __device__ __forceinline__ void cp_commit() {
    asm volatile("cp.async.commit_group;" ::: "memory");
}
static __device__ __forceinline__ void cp_wait1() {
    asm volatile("cp.async.wait_group 1;" ::: "memory");
}
static __device__ __forceinline__ void ldm4(uint32_t* r, uint32_t addr) {
    asm volatile("ldmatrix.sync.aligned.m8n8.x4.shared.b16 {%0,%1,%2,%3}, [%4];"
                 : "=r"(r[0]), "=r"(r[1]), "=r"(r[2]), "=r"(r[3]) : "r"(addr));
}
static __device__ __forceinline__ void mma_f16(float* c, const uint32_t* a, const uint32_t* b) {
    asm("mma.sync.aligned.m16n8k16.row.col.f32.f16.f16.f32 "
        "{%0,%1,%2,%3}, {%4,%5,%6,%7}, {%8,%9}, {%0,%1,%2,%3};"
        : "+f"(c[0]), "+f"(c[1]), "+f"(c[2]), "+f"(c[3])
        : "r"(a[0]), "r"(a[1]), "r"(a[2]), "r"(a[3]), "r"(b[0]), "r"(b[1]));
}

// ---------------- fused prep: zero stats + W prep + feats->fp16 ----------------
__global__ void prep_all_kernel(const float* __restrict__ W1, const float* __restrict__ W2,
                                const float* __restrict__ feats, int n) {
    int b = blockIdx.x, tid = threadIdx.x;
    if (b == 0 && tid < C) {
        g_sum1[tid] = 0.f; g_sq1[tid] = 0.f; g_sum2[tid] = 0.f; g_sq2[tid] = 0.f;
    }
    if (b < 2 * KSZ) {
        int conv = b / KSZ, k = b % KSZ;
        __half* dst = g_wt + (size_t)b * C * C;
        const float* W = ((conv == 0) ? W1 : W2) + (size_t)k * C * C;
        #pragma unroll
        for (int i = 0; i < 16; ++i) {
            int e = tid + i * 256;     // 0..4095
            int c = e >> 6, d = e & 63;
            float v = W[c * C + d];
            uint32_t sseg = (uint32_t)((c >> 3) ^ (d & 7));
            dst[(uint32_t)d * 64u + sseg * 8u + (uint32_t)(c & 7)] = __float2half_rn(v);
        }
        return;
    }
    int i = (b - 2 * KSZ) * 256 + tid;        // float4 index
    int total = n * (C / 4);
    if (i >= total) return;
    float4 v = ((const float4*)feats)[i];
    __half2 a = __floats2half2_rn(v.x, v.y);
    __half2 bb = __floats2half2_rn(v.z, v.w);
    ((uint2*)g_a)[i] = make_uint2(*(uint32_t*)&a, *(uint32_t*)&bb);
}

// y1 -> BN1(inline stats)+ReLU -> fp16 (overwrites g_a)
__global__ void prep_h1_kernel(const float* __restrict__ gamma,
                               const float* __restrict__ beta, int n) {
    __shared__ float s_sc[C], s_sh[C];
    int tid = threadIdx.x;
    if (tid < C) {
        float inv_n = 1.0f / (float)n;
        float mean = g_sum1[tid] * inv_n;
        float var = fmaxf(g_sq1[tid] * inv_n - mean * mean, 0.f);
        float sc = gamma[tid] * rsqrtf(var + EPSV);
        s_sc[tid] = sc;
        s_sh[tid] = beta[tid] - mean * sc;
    }
    __syncthreads();
    int i = blockIdx.x * blockDim.x + tid;
    int total = n * (C / 4);
    if (i >= total) return;
    int c = (i & 15) * 4;
    float4 v = ((const float4*)g_y1)[i];
    v.x = fmaxf(fmaf(v.x, s_sc[c + 0], s_sh[c + 0]), 0.f);
    v.y = fmaxf(fmaf(v.y, s_sc[c + 1], s_sh[c + 1]), 0.f);
    v.z = fmaxf(fmaf(v.z, s_sc[c + 2], s_sh[c + 2]), 0.f);
    v.w = fmaxf(fmaf(v.w, s_sc[c + 3], s_sh[c + 3]), 0.f);
    __half2 a = __floats2half2_rn(v.x, v.y);
    __half2 b = __floats2half2_rn(v.z, v.w);
    ((uint2*)g_a)[i] = make_uint2(*(uint32_t*)&a, *(uint32_t*)&b);
}

// out = relu(bn2(y2)+feats), stats2 inlined
__global__ void final_kernel(const float* __restrict__ feats,
                             const float* __restrict__ gamma,
                             const float* __restrict__ beta,
                             float* __restrict__ out, int n) {
    __shared__ float s_sc[C], s_sh[C];
    int tid = threadIdx.x;
    if (tid < C) {
        float inv_n = 1.0f / (float)n;
        float mean = g_sum2[tid] * inv_n;
        float var = fmaxf(g_sq2[tid] * inv_n - mean * mean, 0.f);
        float sc = gamma[tid] * rsqrtf(var + EPSV);
        s_sc[tid] = sc;
        s_sh[tid] = beta[tid] - mean * sc;
    }
    __syncthreads();
    int i = blockIdx.x * blockDim.x + tid;
    int total = n * (C / 4);
    if (i >= total) return;
    int c = (i & 15) * 4;
    float4 y = ((const float4*)out)[i];
    float4 f = ((const float4*)feats)[i];
    float4 r;
    r.x = fmaxf(fmaf(y.x, s_sc[c + 0], s_sh[c + 0]) + f.x, 0.f);
    r.y = fmaxf(fmaf(y.y, s_sc[c + 1], s_sh[c + 1]) + f.y, 0.f);
    r.z = fmaxf(fmaf(y.z, s_sc[c + 2], s_sh[c + 2]) + f.z, 0.f);
    r.w = fmaxf(fmaf(y.w, s_sc[c + 3], s_sh[c + 3]) + f.w, 0.f);
    ((float4*)out)[i] = r;
}

// ---------------- main conv: R=2/Nc=32 warp tiles, 3-stage ring, 3 CTAs/SM ----------------
template<int PASS>
__global__ __launch_bounds__(256, 3) void conv_mma_kernel(
    const int* __restrict__ nbr, const float* __restrict__ bias,
    float* __restrict__ dout, int n)
{
    extern __shared__ char dsm[];
    __shared__ float s_sum[C], s_sq[C], s_bias[C];

    float*       yout = (PASS == 0) ? g_y1   : dout;
    float*       gsum = (PASS == 0) ? g_sum1 : g_sum2;
    float*       gsq  = (PASS == 0) ? g_sq1  : g_sq2;

    const int tid = threadIdx.x, lane = tid & 31, w = tid >> 5;
    const uint32_t base = (smem_u32(dsm) + 1023u) & ~1023u;

    if (tid < C) { s_sum[tid] = 0.f; s_sq[tid] = 0.f; s_bias[tid] = bias[tid]; }

    // ---- copy-role: 8 segs (16B) per 128B row; 4 rows per thread ----
    const int cseg = tid & 7;
    const int crow = tid >> 3;                 // 0..31
    const long blk0 = (long)blockIdx.x * TM;

    const uint4* gw = (const uint4*)g_wt + (size_t)PASS * KSZ * 512;

    int pidx[4];
    auto load_idx = [&](int k) {
        #pragma unroll
        for (int i = 0; i < 4; ++i) {
            long r = blk0 + crow + 32 * i;
            pidx[i] = (r < (long)n) ? nbr[r * KSZ + k] : 0;
        }
    };
    auto issue_stage = [&](int k) {
        const uint32_t St = base + (uint32_t)(k % 3) * STAGE_BYTES;
        const uint32_t Wst = St + 16384u;
        #pragma unroll
        for (int i = 0; i < 4; ++i) {
            int r = crow + 32 * i;
            uint32_t dst = (uint32_t)r * 128u + (uint32_t)((cseg ^ (r & 7)) << 4);
            cp_async16(St + dst, g_a + (size_t)pidx[i] * 64 + cseg * 8);
        }
        #pragma unroll
        for (int i = 0; i < 2; ++i) {
            int jj = tid + i * 256;
            cp_async16(Wst + (uint32_t)jj * 16u, gw + (size_t)k * 512 + jj);
        }
        cp_commit();
    };

    // ---- mma-role: warp = (rowpair, nhalf); 2 row-tiles x 32 cols ----
    const int nhalf = w & 1, rowpair = w >> 1;
    const int ar0 = rowpair * 32 + (lane & 15);
    const int ahalf = lane >> 4;
    const int ax7 = lane & 7;
    const int bd = ((lane >> 4) & 1) * 8 + (lane & 7);
    const int bkh = (lane >> 3) & 1;
    const int bx7 = bd & 7;
    const uint32_t brow0 = (uint32_t)(nhalf * 32 + bd);

    float acc[2][4][4];
    #pragma unroll
    for (int tt = 0; tt < 2; ++tt)
        #pragma unroll
        for (int nt = 0; nt < 4; ++nt)
            #pragma unroll
            for (int j = 0; j < 4; ++j) acc[tt][nt][j] = 0.f;

    // ---- prologue: fill 2 stages ----
    load_idx(0); issue_stage(0);
    load_idx(1); issue_stage(1);
    load_idx(2);

    for (int k = 0; k < KSZ; ++k) {
        cp_wait1();
        __syncthreads();          // stage k ready; ring slot (k+2)%3 free

        if (k + 2 < KSZ) {
            issue_stage(k + 2);
            if (k + 3 < KSZ) load_idx(k + 3);
        }

        const uint32_t St = base + (uint32_t)(k % 3) * STAGE_BYTES;
        const uint32_t Wst = St + 16384u;

        #pragma unroll
        for (int kk = 0; kk < 4; ++kk) {
            uint32_t a0[4], a1[4], b0[4], b1[4];
            uint32_t asel = (uint32_t)(((kk * 2 + ahalf) ^ ax7) << 4);
            uint32_t bsel = (uint32_t)(((kk * 2 + bkh) ^ bx7) << 4);
            ldm4(a0, St + (uint32_t)ar0 * 128u + asel);
            ldm4(a1, St + (uint32_t)(ar0 + 16) * 128u + asel);
            ldm4(b0, Wst + brow0 * 128u + bsel);
            ldm4(b1, Wst + (brow0 + 16u) * 128u + bsel);
            mma_f16(acc[0][0], a0, b0);
            mma_f16(acc[0][1], a0, b0 + 2);
            mma_f16(acc[1][0], a1, b0);
            mma_f16(acc[1][1], a1, b0 + 2);
            mma_f16(acc[0][2], a0, b1);
            mma_f16(acc[0][3], a0, b1 + 2);
            mma_f16(acc[1][2], a1, b1);
            mma_f16(acc[1][3], a1, b1 + 2);
        }
    }

    // ---------------- epilogue ----------------
    const int g = lane >> 2, tig = lane & 3;

    #pragma unroll
    for (int nt = 0; nt < 4; ++nt) {
        int col = nhalf * 32 + nt * 8 + tig * 2;
        float b0 = s_bias[col], b1 = s_bias[col + 1];
        float sv0 = 0.f, sv1 = 0.f, sq0 = 0.f, sq1 = 0.f;
        #pragma unroll
        for (int tt = 0; tt < 2; ++tt) {
            long row0 = blk0 + rowpair * 32 + tt * 16 + g;
            long row1 = row0 + 8;
            bool v0 = row0 < (long)n, v1 = row1 < (long)n;
            float y00 = v0 ? acc[tt][nt][0] + b0 : 0.f;
            float y01 = v0 ? acc[tt][nt][1] + b1 : 0.f;
            float y10 = v1 ? acc[tt][nt][2] + b0 : 0.f;
            float y11 = v1 ? acc[tt][nt][3] + b1 : 0.f;
            if (v0) *(float2*)(yout + (size_t)row0 * C + col) = make_float2(y00, y01);
            if (v1) *(float2*)(yout + (size_t)row1 * C + col) = make_float2(y10, y11);
            sv0 += y00 + y10; sv1 += y01 + y11;
            sq0 += y00 * y00 + y10 * y10; sq1 += y01 * y01 + y11 * y11;
        }
        #pragma unroll
        for (int o = 16; o >= 4; o >>= 1) {
            sv0 += __shfl_xor_sync(0xffffffffu, sv0, o);
            sv1 += __shfl_xor_sync(0xffffffffu, sv1, o);
            sq0 += __shfl_xor_sync(0xffffffffu, sq0, o);
            sq1 += __shfl_xor_sync(0xffffffffu, sq1, o);
        }
        if (lane < 4) {
            atomicAdd(&s_sum[nhalf * 32 + nt * 8 + lane * 2],     sv0);
            atomicAdd(&s_sum[nhalf * 32 + nt * 8 + lane * 2 + 1], sv1);
            atomicAdd(&s_sq[nhalf * 32 + nt * 8 + lane * 2],      sq0);
            atomicAdd(&s_sq[nhalf * 32 + nt * 8 + lane * 2 + 1],  sq1);
        }
    }
    __syncthreads();
    if (tid < C) { atomicAdd(&gsum[tid], s_sum[tid]); atomicAdd(&gsq[tid], s_sq[tid]); }
}

extern "C" void kernel_launch(void* const* d_in, const int* in_sizes, int n_in,
                              void* d_out, int out_size) {
    const float* feats = (const float*)d_in[0];
    const int*   nbr   = (const int*)d_in[1];
    const float* W1    = (const float*)d_in[2];
    const float* b1    = (const float*)d_in[3];
    const float* g1    = (const float*)d_in[4];
    const float* be1   = (const float*)d_in[5];
    const float* W2    = (const float*)d_in[6];
    const float* b2    = (const float*)d_in[7];
    const float* g2    = (const float*)d_in[8];
    const float* be2   = (const float*)d_in[9];
    float* out = (float*)d_out;

    int n = in_sizes[0] / C;
    int conv_blocks = (n + TM - 1) / TM;
    int ew_blocks = (n * (C / 4) + 255) / 256;

    cudaFuncSetAttribute(conv_mma_kernel<0>, cudaFuncAttributeMaxDynamicSharedMemorySize, SMEM_DYN);
    cudaFuncSetAttribute(conv_mma_kernel<1>, cudaFuncAttributeMaxDynamicSharedMemorySize, SMEM_DYN);

    prep_all_kernel<<<2 * KSZ + ew_blocks, 256>>>(W1, W2, feats, n);
    conv_mma_kernel<0><<<conv_blocks, 256, SMEM_DYN>>>(nbr, b1, nullptr, n);
    prep_h1_kernel<<<ew_blocks, 256>>>(g1, be1, n);
    conv_mma_kernel<1><<<conv_blocks, 256, SMEM_DYN>>>(nbr, b2, out, n);
    final_kernel<<<ew_blocks, 256>>>(feats, g2, be2, out, n);
}